// round 3
// baseline (speedup 1.0000x reference)
#include <cuda_runtime.h>
#include <math.h>

#define NN 100000
#define EE 800000
#define HH 128
#define G4 512
#define TT 200
#define BB 32
#define INQ 64
#define MAXT 1024
#define MAXSLOTS (MAXT + 8)
#define MAXL1 131072

// ---------------- device scratch (no allocs allowed) ----------------
__device__ float g_deg[NN];
__device__ int   g_flag[NN];
__device__ int   g_cnt[4];          // 0=slotCount 1=tgtEdgeCount 2=l1EdgeCount
__device__ int   g_tgt_src[MAXT];
__device__ int   g_tgt_t[MAXT];
__device__ int   g_tgt_slot[MAXT];
__device__ int   g_nodeOfSlot[MAXSLOTS];
__device__ int   g_l1_src[MAXL1];
__device__ int   g_l1_slot[MAXL1];
__device__ float g_h1[MAXSLOTS * HH];
__device__ float g_xw2[MAXSLOTS * HH];
__device__ float g_dvec[9 * HH];
__device__ float g_fw[9 * HH];
__device__ float g_xpre[TT * BB * G4];   // LSTM1 input gates (x-part + biases)
__device__ float g_h1out[BB * HH];       // LSTM1 final hidden
__device__ float g_xpre2[BB * G4];       // LSTM2 input gates

__device__ __forceinline__ float sigf(float x) { return 1.f / (1.f + expf(-x)); }

// ---------------- zero scratch ----------------
__global__ void k_zero() {
    int i = blockIdx.x * 256 + threadIdx.x;
    if (i < NN) { g_deg[i] = 0.f; g_flag[i] = 0; }
    if (i < MAXSLOTS * HH) g_h1[i] = 0.f;
    if (i < 4) g_cnt[i] = 0;
}

// ---------------- edge pass 1: degree histogram + edges into targets ----------------
__global__ void k_scan1(const int* __restrict__ ei) {
    int e = blockIdx.x * 256 + threadIdx.x;
    if (e >= EE) return;
    int d = ei[EE + e];
    atomicAdd(&g_deg[d], 1.0f);
    if (d <= 7000 && (d % 1000) == 0) {   // TARGET = {0,1000,...,7000}
        int ti = d / 1000;
        int p = atomicAdd(&g_cnt[1], 1);
        if (p < MAXT) { g_tgt_src[p] = ei[e]; g_tgt_t[p] = ti; }
    }
}

// ---------------- dedupe target-edge sources into slots; slots 0..7 = targets ----------------
__global__ void k_dedupe() {
    __shared__ int s_src[MAXT];
    __shared__ int s_first[MAXT];
    __shared__ int s_slot[MAXT];
    int i = threadIdx.x;
    int nT = g_cnt[1]; if (nT > MAXT) nT = MAXT;
    if (i < 8) { g_flag[i * 1000] = i + 1; g_nodeOfSlot[i] = i * 1000; }
    int s = (i < nT) ? g_tgt_src[i] : -1;
    s_src[i] = s;
    __syncthreads();
    int slot = -1, first = 0;
    if (i < nT) {
        #pragma unroll
        for (int k = 0; k < 8; k++) if (s == k * 1000) slot = k;
        if (slot < 0) {
            first = 1;
            for (int j = 0; j < i; j++) if (s_src[j] == s) { first = 0; break; }
        }
    }
    s_first[i] = (i < nT && slot < 0) ? first : 0;
    s_slot[i] = slot;
    __syncthreads();
    if (i < nT && slot < 0) {
        if (first) {
            int rank = 0;
            for (int j = 0; j < i; j++) rank += s_first[j];
            s_slot[i] = 8 + rank;
        } else {
            int j = 0; while (s_src[j] != s) j++;
            int rj = 0;
            for (int q = 0; q < j; q++) rj += s_first[q];
            s_slot[i] = 8 + rj;
        }
    }
    __syncthreads();
    if (i < nT) {
        g_tgt_slot[i] = s_slot[i];
        if (s_first[i]) { g_nodeOfSlot[s_slot[i]] = s_src[i]; g_flag[s_src[i]] = s_slot[i] + 1; }
    }
    if (i == 0) {
        int tot = 0;
        for (int j = 0; j < nT; j++) tot += s_first[j];
        g_cnt[0] = 8 + tot;
    }
}

// ---------------- edge pass 2: edges whose dst is in the 1-hop set ----------------
__global__ void k_scan2(const int* __restrict__ ei) {
    int e = blockIdx.x * 256 + threadIdx.x;
    if (e >= EE) return;
    int d = ei[EE + e];
    int f = g_flag[d];
    if (f > 0) {
        int p = atomicAdd(&g_cnt[2], 1);
        if (p < MAXL1) { g_l1_src[p] = ei[e]; g_l1_slot[p] = f - 1; }
    }
}

// ---------------- GCN layer 1: edge messages (sparse, on-demand x@W1 matvec) ----------------
__global__ void k_l1edge(const float* __restrict__ x, const float* __restrict__ W1) {
    __shared__ float xs[HH];
    int cnt = g_cnt[2]; if (cnt > MAXL1) cnt = MAXL1;
    for (int idx = blockIdx.x; idx < cnt; idx += gridDim.x) {
        int src = g_l1_src[idx], slot = g_l1_slot[idx];
        int dn = g_nodeOfSlot[slot];
        float norm = rsqrtf(g_deg[src] + 1.f) * rsqrtf(g_deg[dn] + 1.f);
        __syncthreads();
        xs[threadIdx.x] = x[src * HH + threadIdx.x];
        __syncthreads();
        float acc = 0.f;
        #pragma unroll 8
        for (int k = 0; k < HH; k++) acc += xs[k] * W1[k * HH + threadIdx.x];
        atomicAdd(&g_h1[slot * HH + threadIdx.x], acc * norm);
    }
}

// ---------------- GCN layer 1: self-loop + bias + relu ----------------
__global__ void k_l1self(const float* __restrict__ x, const float* __restrict__ W1,
                         const float* __restrict__ b1) {
    __shared__ float xs[HH];
    int nslots = g_cnt[0];
    for (int slot = blockIdx.x; slot < nslots; slot += gridDim.x) {
        int node = g_nodeOfSlot[slot];
        float rs = rsqrtf(g_deg[node] + 1.f);
        float di2 = rs * rs;
        __syncthreads();
        xs[threadIdx.x] = x[node * HH + threadIdx.x];
        __syncthreads();
        float acc = 0.f;
        #pragma unroll 8
        for (int k = 0; k < HH; k++) acc += xs[k] * W1[k * HH + threadIdx.x];
        float v = g_h1[slot * HH + threadIdx.x] + acc * di2 + b1[threadIdx.x];
        g_h1[slot * HH + threadIdx.x] = fmaxf(v, 0.f);
    }
}

// ---------------- GCN layer 2: h1 @ W2 per slot ----------------
__global__ void k_xw2(const float* __restrict__ W2) {
    __shared__ float hs[HH];
    int nslots = g_cnt[0];
    for (int slot = blockIdx.x; slot < nslots; slot += gridDim.x) {
        __syncthreads();
        hs[threadIdx.x] = g_h1[slot * HH + threadIdx.x];
        __syncthreads();
        float acc = 0.f;
        #pragma unroll 8
        for (int k = 0; k < HH; k++) acc += hs[k] * W2[k * HH + threadIdx.x];
        g_xw2[slot * HH + threadIdx.x] = acc;
    }
}

// ---------------- GCN layer 2: aggregate at the 8 targets -> g_dvec[0:1024] ----------------
__global__ void k_l2tgt(const float* __restrict__ b2) {
    int t = blockIdx.x, o = threadIdx.x;
    int tn = t * 1000;
    float dt = rsqrtf(g_deg[tn] + 1.f);
    float acc = g_xw2[t * HH + o] * dt * dt;
    int cnt = g_cnt[1]; if (cnt > MAXT) cnt = MAXT;
    for (int i = 0; i < cnt; i++) {
        if (g_tgt_t[i] == t) {
            int s = g_tgt_src[i];
            acc += g_xw2[g_tgt_slot[i] * HH + o] * rsqrtf(g_deg[s] + 1.f) * dt;
        }
    }
    acc += b2[o];
    g_dvec[t * HH + o] = fmaxf(acc, 0.f);
}

// ---------------- LSTM1 input GEMM: xpre[t*32+b, n] = data0[b,t,:] @ Wih1[n,:] + bih1+bhh1 ----------------
__global__ __launch_bounds__(256) void k_xpre(const float* __restrict__ data0,
                                              const float* __restrict__ Wih1,
                                              const float* __restrict__ bih1,
                                              const float* __restrict__ bhh1) {
    __shared__ float xs[64][65];
    __shared__ float ws[64][65];   // ws[k][j]
    int rowbase = blockIdx.x * 64;
    int colbase = blockIdx.y * 64;
    int tid = threadIdx.x;
    for (int idx = tid; idx < 64 * 64; idx += 256) {
        int i = idx >> 6, k = idx & 63;
        int r = rowbase + i, b = r & 31, t = r >> 5;
        xs[i][k] = data0[(b * TT + t) * INQ + k];
    }
    for (int idx = tid; idx < 64 * 64; idx += 256) {
        int j = idx >> 6, k = idx & 63;
        ws[k][j] = Wih1[(colbase + j) * INQ + k];
    }
    __syncthreads();
    int tx = tid & 15, ty = tid >> 4;
    float acc[4][4] = {};
    #pragma unroll 8
    for (int k = 0; k < 64; k++) {
        float a[4], bb[4];
        #pragma unroll
        for (int u = 0; u < 4; u++) a[u] = xs[ty * 4 + u][k];
        #pragma unroll
        for (int v = 0; v < 4; v++) bb[v] = ws[k][tx * 4 + v];
        #pragma unroll
        for (int u = 0; u < 4; u++)
            #pragma unroll
            for (int v = 0; v < 4; v++) acc[u][v] = fmaf(a[u], bb[v], acc[u][v]);
    }
    #pragma unroll
    for (int u = 0; u < 4; u++) {
        int r = rowbase + ty * 4 + u;
        #pragma unroll
        for (int v = 0; v < 4; v++) {
            int n = colbase + tx * 4 + v;
            g_xpre[r * G4 + n] = acc[u][v] + bih1[n] + bhh1[n];
        }
    }
}

// ---------------- LSTM1 recurrence: one CTA per batch element ----------------
__global__ __launch_bounds__(512) void k_lstm1(const float* __restrict__ Whh1) {
    int b = blockIdx.x, tid = threadIdx.x;
    __shared__ __align__(16) float sh_h[HH];
    __shared__ float sh_c[HH];
    __shared__ float sh_g[G4];
    if (tid < HH) { sh_h[tid] = 0.f; sh_c[tid] = 0.f; }
    __syncthreads();
    const float4* w4 = (const float4*)(Whh1 + tid * HH);
    for (int t = 0; t < TT; t++) {
        float acc = g_xpre[(t * BB + b) * G4 + tid];
        const float4* h4 = (const float4*)sh_h;
        float a0 = 0.f, a1 = 0.f, a2 = 0.f, a3 = 0.f;
        #pragma unroll
        for (int kk = 0; kk < 32; kk++) {
            float4 w = __ldg(&w4[kk]);
            float4 h = h4[kk];
            a0 = fmaf(w.x, h.x, a0); a1 = fmaf(w.y, h.y, a1);
            a2 = fmaf(w.z, h.z, a2); a3 = fmaf(w.w, h.w, a3);
        }
        sh_g[tid] = acc + ((a0 + a1) + (a2 + a3));
        __syncthreads();
        if (tid < HH) {
            float gi = sh_g[tid], gf = sh_g[HH + tid], gg = sh_g[2 * HH + tid], go = sh_g[3 * HH + tid];
            float c = sigf(gf) * sh_c[tid] + sigf(gi) * tanhf(gg);
            sh_c[tid] = c;
            sh_h[tid] = sigf(go) * tanhf(c);
        }
        __syncthreads();
    }
    if (tid < HH) g_h1out[b * HH + tid] = sh_h[tid];
}

// ---------------- LSTM2 input GEMM: xpre2[s, n] = h1out[s,:] @ Wih2[n,:] + biases ----------------
__global__ __launch_bounds__(128) void k_xpre2(const float* __restrict__ Wih2,
                                               const float* __restrict__ bih2,
                                               const float* __restrict__ bhh2) {
    __shared__ float hh[BB * HH];
    int tid = threadIdx.x;
    for (int idx = tid; idx < BB * HH; idx += 128) hh[idx] = g_h1out[idx];
    __syncthreads();
    int n = blockIdx.x * 128 + tid;
    float4 wreg[32];
    const float4* w4 = (const float4*)(Wih2 + n * HH);
    #pragma unroll
    for (int kk = 0; kk < 32; kk++) wreg[kk] = __ldg(&w4[kk]);
    float bias = bih2[n] + bhh2[n];
    for (int s = 0; s < BB; s++) {
        const float4* h4 = (const float4*)(hh + s * HH);
        float a0 = 0.f, a1 = 0.f, a2 = 0.f, a3 = 0.f;
        #pragma unroll
        for (int kk = 0; kk < 32; kk++) {
            float4 h = h4[kk];
            a0 = fmaf(wreg[kk].x, h.x, a0); a1 = fmaf(wreg[kk].y, h.y, a1);
            a2 = fmaf(wreg[kk].z, h.z, a2); a3 = fmaf(wreg[kk].w, h.w, a3);
        }
        g_xpre2[s * G4 + n] = bias + ((a0 + a1) + (a2 + a3));
    }
}

// ---------------- LSTM2 recurrence: batch=1, 32 steps, one CTA ----------------
__global__ __launch_bounds__(512) void k_lstm2(const float* __restrict__ Whh2) {
    int tid = threadIdx.x;
    __shared__ __align__(16) float sh_h[HH];
    __shared__ float sh_c[HH];
    __shared__ float sh_g[G4];
    if (tid < HH) { sh_h[tid] = 0.f; sh_c[tid] = 0.f; }
    __syncthreads();
    const float4* w4 = (const float4*)(Whh2 + tid * HH);
    for (int s = 0; s < BB; s++) {
        float acc = g_xpre2[s * G4 + tid];
        const float4* h4 = (const float4*)sh_h;
        float a0 = 0.f, a1 = 0.f, a2 = 0.f, a3 = 0.f;
        #pragma unroll
        for (int kk = 0; kk < 32; kk++) {
            float4 w = __ldg(&w4[kk]);
            float4 h = h4[kk];
            a0 = fmaf(w.x, h.x, a0); a1 = fmaf(w.y, h.y, a1);
            a2 = fmaf(w.z, h.z, a2); a3 = fmaf(w.w, h.w, a3);
        }
        sh_g[tid] = acc + ((a0 + a1) + (a2 + a3));
        __syncthreads();
        if (tid < HH) {
            float gi = sh_g[tid], gf = sh_g[HH + tid], gg = sh_g[2 * HH + tid], go = sh_g[3 * HH + tid];
            float c = sigf(gf) * sh_c[tid] + sigf(gi) * tanhf(gg);
            sh_c[tid] = c;
            sh_h[tid] = sigf(go) * tanhf(c);
        }
        __syncthreads();
    }
    if (tid < HH) g_dvec[8 * HH + tid] = sh_h[tid];
}

// ---------------- MLP head: fuse m1_w @ m2_w (no nonlinearity in head) ----------------
__global__ void k_fw(const float* __restrict__ m1w, const float* __restrict__ m2w) {
    int i = blockIdx.x;
    float s = 0.f;
    for (int j = threadIdx.x; j < 576; j += 64) s += m1w[i * 576 + j] * m2w[j];
    #pragma unroll
    for (int off = 16; off > 0; off >>= 1) s += __shfl_down_sync(0xffffffffu, s, off);
    __shared__ float sm[2];
    if ((threadIdx.x & 31) == 0) sm[threadIdx.x >> 5] = s;
    __syncthreads();
    if (threadIdx.x == 0) g_fw[i] = sm[0] + sm[1];
}

__global__ void k_final(const float* __restrict__ m1b, const float* __restrict__ m2w,
                        const float* __restrict__ m2b, float* __restrict__ out) {
    __shared__ float red[512];
    float s = 0.f;
    for (int i = threadIdx.x; i < 9 * HH; i += 512) s += g_dvec[i] * g_fw[i];
    for (int j = threadIdx.x; j < 576; j += 512) s += m1b[j] * m2w[j];
    red[threadIdx.x] = s;
    __syncthreads();
    for (int st = 256; st > 0; st >>= 1) {
        if (threadIdx.x < st) red[threadIdx.x] += red[threadIdx.x + st];
        __syncthreads();
    }
    if (threadIdx.x == 0) out[0] = red[0] + m2b[0];
}

// ---------------- launch ----------------
extern "C" void kernel_launch(void* const* d_in, const int* in_sizes, int n_in,
                              void* d_out, int out_size) {
    const float* data0 = (const float*)d_in[0];
    const float* data1 = (const float*)d_in[1];
    const int*   ei    = (const int*)d_in[2];
    const float* W1   = (const float*)d_in[3];
    const float* b1   = (const float*)d_in[4];
    const float* W2   = (const float*)d_in[5];
    const float* b2   = (const float*)d_in[6];
    const float* Wih1 = (const float*)d_in[7];
    const float* Whh1 = (const float*)d_in[8];
    const float* bih1 = (const float*)d_in[9];
    const float* bhh1 = (const float*)d_in[10];
    const float* Wih2 = (const float*)d_in[11];
    const float* Whh2 = (const float*)d_in[12];
    const float* bih2 = (const float*)d_in[13];
    const float* bhh2 = (const float*)d_in[14];
    const float* m1w  = (const float*)d_in[15];
    const float* m1b  = (const float*)d_in[16];
    const float* m2w  = (const float*)d_in[17];
    const float* m2b  = (const float*)d_in[18];
    float* out = (float*)d_out;

    k_zero<<<(MAXSLOTS * HH + 255) / 256, 256>>>();
    k_scan1<<<(EE + 255) / 256, 256>>>(ei);
    k_dedupe<<<1, MAXT>>>();
    k_scan2<<<(EE + 255) / 256, 256>>>(ei);
    k_l1edge<<<512, HH>>>(data1, W1);
    k_l1self<<<128, HH>>>(data1, W1, b1);
    k_xw2<<<128, HH>>>(W2);
    k_l2tgt<<<8, HH>>>(b2);
    k_xpre<<<dim3(100, 8), 256>>>(data0, Wih1, bih1, bhh1);
    k_lstm1<<<BB, 512>>>(Whh1);
    k_xpre2<<<4, 128>>>(Wih2, bih2, bhh2);
    k_lstm2<<<1, 512>>>(Whh2);
    k_fw<<<1152, 64>>>(m1w, m2w);
    k_final<<<1, 512>>>(m1b, m2w, m2b, out);
}

// round 4
// speedup vs baseline: 5.1179x; 5.1179x over previous
#include <cuda_runtime.h>
#include <math.h>

#define NN 100000
#define EE 800000
#define HH 128
#define G4 512
#define TT 200
#define BB 32
#define INQ 64
#define MAXT 1024
#define MAXSLOTS (MAXT + 8)
#define MAXL1 131072
#define PADQ 513
#define LSTM_DYN_SMEM (16 * PADQ * 16)   // float4 sw4[16][513] = 131328 B

// ---------------- device scratch (no allocs allowed) ----------------
__device__ float g_deg[NN];
__device__ int   g_flag[NN];
__device__ int   g_cnt[4];          // 0=slotCount 1=tgtEdgeCount 2=l1EdgeCount
__device__ int   g_tgt_src[MAXT];
__device__ int   g_tgt_t[MAXT];
__device__ int   g_tgt_slot[MAXT];
__device__ int   g_nodeOfSlot[MAXSLOTS];
__device__ int   g_l1_src[MAXL1];
__device__ int   g_l1_slot[MAXL1];
__device__ float g_h1[MAXSLOTS * HH];
__device__ float g_xw2[MAXSLOTS * HH];
__device__ float g_dvec[9 * HH];
__device__ float g_fw[9 * HH];
__device__ float g_xpre[TT * BB * G4];   // LSTM1 input gates (x-part + biases)
__device__ float g_h1out[BB * HH];       // LSTM1 final hidden
__device__ float g_xpre2[BB * G4];       // LSTM2 input gates

__device__ __forceinline__ float sigf(float x) { return 1.f / (1.f + expf(-x)); }

// ---------------- zero scratch ----------------
__global__ void k_zero() {
    int i = blockIdx.x * 256 + threadIdx.x;
    if (i < NN) { g_deg[i] = 0.f; g_flag[i] = 0; }
    if (i < MAXSLOTS * HH) g_h1[i] = 0.f;
    if (i < 4) g_cnt[i] = 0;
}

// ---------------- edge pass 1: degree histogram + edges into targets ----------------
__global__ void k_scan1(const int* __restrict__ ei) {
    int e = blockIdx.x * 256 + threadIdx.x;
    if (e >= EE) return;
    int d = ei[EE + e];
    atomicAdd(&g_deg[d], 1.0f);
    if (d <= 7000 && (d % 1000) == 0) {   // TARGET = {0,1000,...,7000}
        int ti = d / 1000;
        int p = atomicAdd(&g_cnt[1], 1);
        if (p < MAXT) { g_tgt_src[p] = ei[e]; g_tgt_t[p] = ti; }
    }
}

// ---------------- dedupe target-edge sources into slots; slots 0..7 = targets ----------------
__global__ void k_dedupe() {
    __shared__ int s_src[MAXT];
    __shared__ int s_first[MAXT];
    __shared__ int s_slot[MAXT];
    int i = threadIdx.x;
    int nT = g_cnt[1]; if (nT > MAXT) nT = MAXT;
    if (i < 8) { g_flag[i * 1000] = i + 1; g_nodeOfSlot[i] = i * 1000; }
    int s = (i < nT) ? g_tgt_src[i] : -1;
    s_src[i] = s;
    __syncthreads();
    int slot = -1, first = 0;
    if (i < nT) {
        #pragma unroll
        for (int k = 0; k < 8; k++) if (s == k * 1000) slot = k;
        if (slot < 0) {
            first = 1;
            for (int j = 0; j < i; j++) if (s_src[j] == s) { first = 0; break; }
        }
    }
    s_first[i] = (i < nT && slot < 0) ? first : 0;
    s_slot[i] = slot;
    __syncthreads();
    if (i < nT && slot < 0) {
        if (first) {
            int rank = 0;
            for (int j = 0; j < i; j++) rank += s_first[j];
            s_slot[i] = 8 + rank;
        } else {
            int j = 0; while (s_src[j] != s) j++;
            int rj = 0;
            for (int q = 0; q < j; q++) rj += s_first[q];
            s_slot[i] = 8 + rj;
        }
    }
    __syncthreads();
    if (i < nT) {
        g_tgt_slot[i] = s_slot[i];
        if (s_first[i]) { g_nodeOfSlot[s_slot[i]] = s_src[i]; g_flag[s_src[i]] = s_slot[i] + 1; }
    }
    if (i == 0) {
        int tot = 0;
        for (int j = 0; j < nT; j++) tot += s_first[j];
        g_cnt[0] = 8 + tot;
    }
}

// ---------------- edge pass 2: edges whose dst is in the 1-hop set ----------------
__global__ void k_scan2(const int* __restrict__ ei) {
    int e = blockIdx.x * 256 + threadIdx.x;
    if (e >= EE) return;
    int d = ei[EE + e];
    int f = g_flag[d];
    if (f > 0) {
        int p = atomicAdd(&g_cnt[2], 1);
        if (p < MAXL1) { g_l1_src[p] = ei[e]; g_l1_slot[p] = f - 1; }
    }
}

// ---------------- GCN layer 1: edge messages (sparse, on-demand x@W1 matvec) ----------------
__global__ void k_l1edge(const float* __restrict__ x, const float* __restrict__ W1) {
    __shared__ float xs[HH];
    int cnt = g_cnt[2]; if (cnt > MAXL1) cnt = MAXL1;
    for (int idx = blockIdx.x; idx < cnt; idx += gridDim.x) {
        int src = g_l1_src[idx], slot = g_l1_slot[idx];
        int dn = g_nodeOfSlot[slot];
        float norm = rsqrtf(g_deg[src] + 1.f) * rsqrtf(g_deg[dn] + 1.f);
        __syncthreads();
        xs[threadIdx.x] = x[src * HH + threadIdx.x];
        __syncthreads();
        float acc = 0.f;
        #pragma unroll 8
        for (int k = 0; k < HH; k++) acc += xs[k] * W1[k * HH + threadIdx.x];
        atomicAdd(&g_h1[slot * HH + threadIdx.x], acc * norm);
    }
}

// ---------------- GCN layer 1: self-loop + bias + relu ----------------
__global__ void k_l1self(const float* __restrict__ x, const float* __restrict__ W1,
                         const float* __restrict__ b1) {
    __shared__ float xs[HH];
    int nslots = g_cnt[0];
    for (int slot = blockIdx.x; slot < nslots; slot += gridDim.x) {
        int node = g_nodeOfSlot[slot];
        float rs = rsqrtf(g_deg[node] + 1.f);
        float di2 = rs * rs;
        __syncthreads();
        xs[threadIdx.x] = x[node * HH + threadIdx.x];
        __syncthreads();
        float acc = 0.f;
        #pragma unroll 8
        for (int k = 0; k < HH; k++) acc += xs[k] * W1[k * HH + threadIdx.x];
        float v = g_h1[slot * HH + threadIdx.x] + acc * di2 + b1[threadIdx.x];
        g_h1[slot * HH + threadIdx.x] = fmaxf(v, 0.f);
    }
}

// ---------------- GCN layer 2: h1 @ W2 per slot ----------------
__global__ void k_xw2(const float* __restrict__ W2) {
    __shared__ float hs[HH];
    int nslots = g_cnt[0];
    for (int slot = blockIdx.x; slot < nslots; slot += gridDim.x) {
        __syncthreads();
        hs[threadIdx.x] = g_h1[slot * HH + threadIdx.x];
        __syncthreads();
        float acc = 0.f;
        #pragma unroll 8
        for (int k = 0; k < HH; k++) acc += hs[k] * W2[k * HH + threadIdx.x];
        g_xw2[slot * HH + threadIdx.x] = acc;
    }
}

// ---------------- GCN layer 2: aggregate at the 8 targets -> g_dvec[0:1024] ----------------
__global__ void k_l2tgt(const float* __restrict__ b2) {
    int t = blockIdx.x, o = threadIdx.x;
    int tn = t * 1000;
    float dt = rsqrtf(g_deg[tn] + 1.f);
    float acc = g_xw2[t * HH + o] * dt * dt;
    int cnt = g_cnt[1]; if (cnt > MAXT) cnt = MAXT;
    for (int i = 0; i < cnt; i++) {
        if (g_tgt_t[i] == t) {
            int s = g_tgt_src[i];
            acc += g_xw2[g_tgt_slot[i] * HH + o] * rsqrtf(g_deg[s] + 1.f) * dt;
        }
    }
    acc += b2[o];
    g_dvec[t * HH + o] = fmaxf(acc, 0.f);
}

// ---------------- LSTM1 input GEMM: xpre[t*32+b, n] = data0[b,t,:] @ Wih1[n,:] + bih1+bhh1 ----------------
__global__ __launch_bounds__(256) void k_xpre(const float* __restrict__ data0,
                                              const float* __restrict__ Wih1,
                                              const float* __restrict__ bih1,
                                              const float* __restrict__ bhh1) {
    __shared__ float xs[64][65];
    __shared__ float ws[64][65];   // ws[k][j]
    int rowbase = blockIdx.x * 64;
    int colbase = blockIdx.y * 64;
    int tid = threadIdx.x;
    for (int idx = tid; idx < 64 * 64; idx += 256) {
        int i = idx >> 6, k = idx & 63;
        int r = rowbase + i, b = r & 31, t = r >> 5;
        xs[i][k] = data0[(b * TT + t) * INQ + k];
    }
    for (int idx = tid; idx < 64 * 64; idx += 256) {
        int j = idx >> 6, k = idx & 63;
        ws[k][j] = Wih1[(colbase + j) * INQ + k];
    }
    __syncthreads();
    int tx = tid & 15, ty = tid >> 4;
    float acc[4][4] = {};
    #pragma unroll 8
    for (int k = 0; k < 64; k++) {
        float a[4], bb[4];
        #pragma unroll
        for (int u = 0; u < 4; u++) a[u] = xs[ty * 4 + u][k];
        #pragma unroll
        for (int v = 0; v < 4; v++) bb[v] = ws[k][tx * 4 + v];
        #pragma unroll
        for (int u = 0; u < 4; u++)
            #pragma unroll
            for (int v = 0; v < 4; v++) acc[u][v] = fmaf(a[u], bb[v], acc[u][v]);
    }
    #pragma unroll
    for (int u = 0; u < 4; u++) {
        int r = rowbase + ty * 4 + u;
        #pragma unroll
        for (int v = 0; v < 4; v++) {
            int n = colbase + tx * 4 + v;
            g_xpre[r * G4 + n] = acc[u][v] + bih1[n] + bhh1[n];
        }
    }
}

// ---------------- LSTM recurrence: weights in regs (lower half) + padded transposed SMEM (upper half)
// which=1: LSTM1 (grid=BB, reads g_xpre, writes g_h1out)
// which=2: LSTM2 (grid=1, reads g_xpre2, writes g_dvec+8*HH)
__global__ __launch_bounds__(512) void k_lstm(const float* __restrict__ Whh, int steps, int which) {
    extern __shared__ float4 sw4[];            // [16][PADQ]
    __shared__ __align__(16) float sh_h[HH];
    __shared__ float sh_c[HH];
    __shared__ float sh_g[G4];
    int b = blockIdx.x, tid = threadIdx.x;
    const float4* gW4 = (const float4*)Whh;    // row t = gW4[t*32 .. t*32+31]

    // stage LOWER half (k 0..63) via coalesced global -> transposed smem -> regs
    for (int idx = tid; idx < 512 * 16; idx += 512) {
        int t = idx >> 4, q = idx & 15;        // q consecutive -> coalesced read
        sw4[q * PADQ + t] = gW4[t * 32 + q];
    }
    __syncthreads();
    float4 wr[16];
    #pragma unroll
    for (int q = 0; q < 16; q++) wr[q] = sw4[q * PADQ + tid];
    __syncthreads();
    // stage UPPER half (k 64..127) into transposed smem (stays resident)
    for (int idx = tid; idx < 512 * 16; idx += 512) {
        int t = idx >> 4, q = idx & 15;
        sw4[q * PADQ + t] = gW4[t * 32 + 16 + q];
    }
    if (tid < HH) { sh_h[tid] = 0.f; sh_c[tid] = 0.f; }
    __syncthreads();

    const float4* h4 = (const float4*)sh_h;
    for (int s = 0; s < steps; s++) {
        float acc = (which == 1) ? g_xpre[(s * BB + b) * G4 + tid]
                                 : g_xpre2[s * G4 + tid];
        float a0 = 0.f, a1 = 0.f, a2 = 0.f, a3 = 0.f;
        #pragma unroll
        for (int q = 0; q < 16; q++) {
            float4 h = h4[q];
            a0 = fmaf(wr[q].x, h.x, a0); a1 = fmaf(wr[q].y, h.y, a1);
            a2 = fmaf(wr[q].z, h.z, a2); a3 = fmaf(wr[q].w, h.w, a3);
        }
        #pragma unroll
        for (int q = 0; q < 16; q++) {
            float4 w = sw4[q * PADQ + tid];
            float4 h = h4[16 + q];
            a0 = fmaf(w.x, h.x, a0); a1 = fmaf(w.y, h.y, a1);
            a2 = fmaf(w.z, h.z, a2); a3 = fmaf(w.w, h.w, a3);
        }
        sh_g[tid] = acc + ((a0 + a1) + (a2 + a3));
        __syncthreads();
        if (tid < HH) {
            float gi = sh_g[tid], gf = sh_g[HH + tid], gg = sh_g[2 * HH + tid], go = sh_g[3 * HH + tid];
            float c = sigf(gf) * sh_c[tid] + sigf(gi) * tanhf(gg);
            sh_c[tid] = c;
            sh_h[tid] = sigf(go) * tanhf(c);
        }
        __syncthreads();
    }
    if (tid < HH) {
        if (which == 1) g_h1out[b * HH + tid] = sh_h[tid];
        else            g_dvec[8 * HH + tid] = sh_h[tid];
    }
}

// ---------------- LSTM2 input GEMM: xpre2[s, n] = h1out[s,:] @ Wih2[n,:] + biases ----------------
__global__ __launch_bounds__(128) void k_xpre2(const float* __restrict__ Wih2,
                                               const float* __restrict__ bih2,
                                               const float* __restrict__ bhh2) {
    __shared__ float hh[BB * HH];
    int tid = threadIdx.x;
    for (int idx = tid; idx < BB * HH; idx += 128) hh[idx] = g_h1out[idx];
    __syncthreads();
    int n = blockIdx.x * 128 + tid;
    float4 wreg[32];
    const float4* w4 = (const float4*)(Wih2 + n * HH);
    #pragma unroll
    for (int kk = 0; kk < 32; kk++) wreg[kk] = __ldg(&w4[kk]);
    float bias = bih2[n] + bhh2[n];
    for (int s = 0; s < BB; s++) {
        const float4* h4 = (const float4*)(hh + s * HH);
        float a0 = 0.f, a1 = 0.f, a2 = 0.f, a3 = 0.f;
        #pragma unroll
        for (int kk = 0; kk < 32; kk++) {
            float4 h = h4[kk];
            a0 = fmaf(wreg[kk].x, h.x, a0); a1 = fmaf(wreg[kk].y, h.y, a1);
            a2 = fmaf(wreg[kk].z, h.z, a2); a3 = fmaf(wreg[kk].w, h.w, a3);
        }
        g_xpre2[s * G4 + n] = bias + ((a0 + a1) + (a2 + a3));
    }
}

// ---------------- MLP head: fuse m1_w @ m2_w (no nonlinearity in head) ----------------
__global__ void k_fw(const float* __restrict__ m1w, const float* __restrict__ m2w) {
    int i = blockIdx.x;
    float s = 0.f;
    for (int j = threadIdx.x; j < 576; j += 64) s += m1w[i * 576 + j] * m2w[j];
    #pragma unroll
    for (int off = 16; off > 0; off >>= 1) s += __shfl_down_sync(0xffffffffu, s, off);
    __shared__ float sm[2];
    if ((threadIdx.x & 31) == 0) sm[threadIdx.x >> 5] = s;
    __syncthreads();
    if (threadIdx.x == 0) g_fw[i] = sm[0] + sm[1];
}

__global__ void k_final(const float* __restrict__ m1b, const float* __restrict__ m2w,
                        const float* __restrict__ m2b, float* __restrict__ out) {
    __shared__ float red[512];
    float s = 0.f;
    for (int i = threadIdx.x; i < 9 * HH; i += 512) s += g_dvec[i] * g_fw[i];
    for (int j = threadIdx.x; j < 576; j += 512) s += m1b[j] * m2w[j];
    red[threadIdx.x] = s;
    __syncthreads();
    for (int st = 256; st > 0; st >>= 1) {
        if (threadIdx.x < st) red[threadIdx.x] += red[threadIdx.x + st];
        __syncthreads();
    }
    if (threadIdx.x == 0) out[0] = red[0] + m2b[0];
}

// ---------------- launch ----------------
extern "C" void kernel_launch(void* const* d_in, const int* in_sizes, int n_in,
                              void* d_out, int out_size) {
    const float* data0 = (const float*)d_in[0];
    const float* data1 = (const float*)d_in[1];
    const int*   ei    = (const int*)d_in[2];
    const float* W1   = (const float*)d_in[3];
    const float* b1   = (const float*)d_in[4];
    const float* W2   = (const float*)d_in[5];
    const float* b2   = (const float*)d_in[6];
    const float* Wih1 = (const float*)d_in[7];
    const float* Whh1 = (const float*)d_in[8];
    const float* bih1 = (const float*)d_in[9];
    const float* bhh1 = (const float*)d_in[10];
    const float* Wih2 = (const float*)d_in[11];
    const float* Whh2 = (const float*)d_in[12];
    const float* bih2 = (const float*)d_in[13];
    const float* bhh2 = (const float*)d_in[14];
    const float* m1w  = (const float*)d_in[15];
    const float* m1b  = (const float*)d_in[16];
    const float* m2w  = (const float*)d_in[17];
    const float* m2b  = (const float*)d_in[18];
    float* out = (float*)d_out;

    static int smem_set = 0;
    if (!smem_set) {
        cudaFuncSetAttribute(k_lstm, cudaFuncAttributeMaxDynamicSharedMemorySize, LSTM_DYN_SMEM);
        smem_set = 1;
    }

    k_zero<<<(MAXSLOTS * HH + 255) / 256, 256>>>();
    k_scan1<<<(EE + 255) / 256, 256>>>(ei);
    k_dedupe<<<1, MAXT>>>();
    k_scan2<<<(EE + 255) / 256, 256>>>(ei);
    k_l1edge<<<512, HH>>>(data1, W1);
    k_l1self<<<128, HH>>>(data1, W1, b1);
    k_xw2<<<128, HH>>>(W2);
    k_l2tgt<<<8, HH>>>(b2);
    k_xpre<<<dim3(100, 8), 256>>>(data0, Wih1, bih1, bhh1);
    k_lstm<<<BB, 512, LSTM_DYN_SMEM>>>(Whh1, TT, 1);
    k_xpre2<<<4, 128>>>(Wih2, bih2, bhh2);
    k_lstm<<<1, 512, LSTM_DYN_SMEM>>>(Whh2, BB, 2);
    k_fw<<<1152, 64>>>(m1w, m2w);
    k_final<<<1, 512>>>(m1b, m2w, m2b, out);
}

// round 5
// speedup vs baseline: 6.4868x; 1.2675x over previous
#include <cuda_runtime.h>
#include <math.h>
#include <stdint.h>

#define NN 100000
#define EE 800000
#define HH 128
#define G4 512
#define TT 200
#define BB 32
#define INQ 64
#define MAXT 1024
#define MAXSLOTS (MAXT + 8)
#define MAXL1 131072

// ---------------- device scratch (no allocs allowed) ----------------
__device__ float g_deg[NN];
__device__ int   g_flag[NN];
__device__ int   g_cnt[4];          // 0=slotCount 1=tgtEdgeCount 2=l1EdgeCount
__device__ int   g_tgt_src[MAXT];
__device__ int   g_tgt_t[MAXT];
__device__ int   g_tgt_slot[MAXT];
__device__ int   g_nodeOfSlot[MAXSLOTS];
__device__ int   g_l1_src[MAXL1];
__device__ int   g_l1_slot[MAXL1];
__device__ float g_h1[MAXSLOTS * HH];
__device__ float g_xw2[MAXSLOTS * HH];
__device__ float g_dvec[9 * HH];
__device__ float g_fw[9 * HH];
__device__ float g_xpre[TT * BB * G4];   // LSTM1 input gates (x-part + biases)
__device__ float g_h1out[BB * HH];       // LSTM1 final hidden
__device__ float g_xpre2[BB * G4];       // LSTM2 input gates

__device__ __forceinline__ float sigf(float x) { return 1.f / (1.f + expf(-x)); }

// ---------------- zero scratch ----------------
__global__ void k_zero() {
    int i = blockIdx.x * 256 + threadIdx.x;
    if (i < NN) { g_deg[i] = 0.f; g_flag[i] = 0; }
    if (i < MAXSLOTS * HH) g_h1[i] = 0.f;
    if (i < 4) g_cnt[i] = 0;
}

// ---------------- edge pass 1: degree histogram + edges into targets ----------------
__global__ void k_scan1(const int* __restrict__ ei) {
    int e = blockIdx.x * 256 + threadIdx.x;
    if (e >= EE) return;
    int d = ei[EE + e];
    atomicAdd(&g_deg[d], 1.0f);
    if (d <= 7000 && (d % 1000) == 0) {   // TARGET = {0,1000,...,7000}
        int ti = d / 1000;
        int p = atomicAdd(&g_cnt[1], 1);
        if (p < MAXT) { g_tgt_src[p] = ei[e]; g_tgt_t[p] = ti; }
    }
}

// ---------------- dedupe target-edge sources into slots; slots 0..7 = targets ----------------
__global__ void k_dedupe() {
    __shared__ int s_src[MAXT];
    __shared__ int s_first[MAXT];
    __shared__ int s_slot[MAXT];
    int i = threadIdx.x;
    int nT = g_cnt[1]; if (nT > MAXT) nT = MAXT;
    if (i < 8) { g_flag[i * 1000] = i + 1; g_nodeOfSlot[i] = i * 1000; }
    int s = (i < nT) ? g_tgt_src[i] : -1;
    s_src[i] = s;
    __syncthreads();
    int slot = -1, first = 0;
    if (i < nT) {
        #pragma unroll
        for (int k = 0; k < 8; k++) if (s == k * 1000) slot = k;
        if (slot < 0) {
            first = 1;
            for (int j = 0; j < i; j++) if (s_src[j] == s) { first = 0; break; }
        }
    }
    s_first[i] = (i < nT && slot < 0) ? first : 0;
    s_slot[i] = slot;
    __syncthreads();
    if (i < nT && slot < 0) {
        if (first) {
            int rank = 0;
            for (int j = 0; j < i; j++) rank += s_first[j];
            s_slot[i] = 8 + rank;
        } else {
            int j = 0; while (s_src[j] != s) j++;
            int rj = 0;
            for (int q = 0; q < j; q++) rj += s_first[q];
            s_slot[i] = 8 + rj;
        }
    }
    __syncthreads();
    if (i < nT) {
        g_tgt_slot[i] = s_slot[i];
        if (s_first[i]) { g_nodeOfSlot[s_slot[i]] = s_src[i]; g_flag[s_src[i]] = s_slot[i] + 1; }
    }
    if (i == 0) {
        int tot = 0;
        for (int j = 0; j < nT; j++) tot += s_first[j];
        g_cnt[0] = 8 + tot;
    }
}

// ---------------- edge pass 2: edges whose dst is in the 1-hop set ----------------
__global__ void k_scan2(const int* __restrict__ ei) {
    int e = blockIdx.x * 256 + threadIdx.x;
    if (e >= EE) return;
    int d = ei[EE + e];
    int f = g_flag[d];
    if (f > 0) {
        int p = atomicAdd(&g_cnt[2], 1);
        if (p < MAXL1) { g_l1_src[p] = ei[e]; g_l1_slot[p] = f - 1; }
    }
}

// ---------------- GCN layer 1: edge messages (sparse, on-demand x@W1 matvec) ----------------
__global__ void k_l1edge(const float* __restrict__ x, const float* __restrict__ W1) {
    __shared__ float xs[HH];
    int cnt = g_cnt[2]; if (cnt > MAXL1) cnt = MAXL1;
    for (int idx = blockIdx.x; idx < cnt; idx += gridDim.x) {
        int src = g_l1_src[idx], slot = g_l1_slot[idx];
        int dn = g_nodeOfSlot[slot];
        float norm = rsqrtf(g_deg[src] + 1.f) * rsqrtf(g_deg[dn] + 1.f);
        __syncthreads();
        xs[threadIdx.x] = x[src * HH + threadIdx.x];
        __syncthreads();
        float acc = 0.f;
        #pragma unroll 8
        for (int k = 0; k < HH; k++) acc += xs[k] * W1[k * HH + threadIdx.x];
        atomicAdd(&g_h1[slot * HH + threadIdx.x], acc * norm);
    }
}

// ---------------- GCN layer 1: self-loop + bias + relu ----------------
__global__ void k_l1self(const float* __restrict__ x, const float* __restrict__ W1,
                         const float* __restrict__ b1) {
    __shared__ float xs[HH];
    int nslots = g_cnt[0];
    for (int slot = blockIdx.x; slot < nslots; slot += gridDim.x) {
        int node = g_nodeOfSlot[slot];
        float rs = rsqrtf(g_deg[node] + 1.f);
        float di2 = rs * rs;
        __syncthreads();
        xs[threadIdx.x] = x[node * HH + threadIdx.x];
        __syncthreads();
        float acc = 0.f;
        #pragma unroll 8
        for (int k = 0; k < HH; k++) acc += xs[k] * W1[k * HH + threadIdx.x];
        float v = g_h1[slot * HH + threadIdx.x] + acc * di2 + b1[threadIdx.x];
        g_h1[slot * HH + threadIdx.x] = fmaxf(v, 0.f);
    }
}

// ---------------- GCN layer 2: h1 @ W2 per slot ----------------
__global__ void k_xw2(const float* __restrict__ W2) {
    __shared__ float hs[HH];
    int nslots = g_cnt[0];
    for (int slot = blockIdx.x; slot < nslots; slot += gridDim.x) {
        __syncthreads();
        hs[threadIdx.x] = g_h1[slot * HH + threadIdx.x];
        __syncthreads();
        float acc = 0.f;
        #pragma unroll 8
        for (int k = 0; k < HH; k++) acc += hs[k] * W2[k * HH + threadIdx.x];
        g_xw2[slot * HH + threadIdx.x] = acc;
    }
}

// ---------------- GCN layer 2: aggregate at the 8 targets -> g_dvec[0:1024] ----------------
__global__ void k_l2tgt(const float* __restrict__ b2) {
    int t = blockIdx.x, o = threadIdx.x;
    int tn = t * 1000;
    float dt = rsqrtf(g_deg[tn] + 1.f);
    float acc = g_xw2[t * HH + o] * dt * dt;
    int cnt = g_cnt[1]; if (cnt > MAXT) cnt = MAXT;
    for (int i = 0; i < cnt; i++) {
        if (g_tgt_t[i] == t) {
            int s = g_tgt_src[i];
            acc += g_xw2[g_tgt_slot[i] * HH + o] * rsqrtf(g_deg[s] + 1.f) * dt;
        }
    }
    acc += b2[o];
    g_dvec[t * HH + o] = fmaxf(acc, 0.f);
}

// ---------------- LSTM1 input GEMM: xpre[t*32+b, n] = data0[b,t,:] @ Wih1[n,:] + bih1+bhh1 ----------------
__global__ __launch_bounds__(256) void k_xpre(const float* __restrict__ data0,
                                              const float* __restrict__ Wih1,
                                              const float* __restrict__ bih1,
                                              const float* __restrict__ bhh1) {
    __shared__ float xs[64][65];
    __shared__ float ws[64][65];   // ws[k][j]
    int rowbase = blockIdx.x * 64;
    int colbase = blockIdx.y * 64;
    int tid = threadIdx.x;
    for (int idx = tid; idx < 64 * 64; idx += 256) {
        int i = idx >> 6, k = idx & 63;
        int r = rowbase + i, b = r & 31, t = r >> 5;
        xs[i][k] = data0[(b * TT + t) * INQ + k];
    }
    for (int idx = tid; idx < 64 * 64; idx += 256) {
        int j = idx >> 6, k = idx & 63;
        ws[k][j] = Wih1[(colbase + j) * INQ + k];
    }
    __syncthreads();
    int tx = tid & 15, ty = tid >> 4;
    float acc[4][4] = {};
    #pragma unroll 8
    for (int k = 0; k < 64; k++) {
        float a[4], bb[4];
        #pragma unroll
        for (int u = 0; u < 4; u++) a[u] = xs[ty * 4 + u][k];
        #pragma unroll
        for (int v = 0; v < 4; v++) bb[v] = ws[k][tx * 4 + v];
        #pragma unroll
        for (int u = 0; u < 4; u++)
            #pragma unroll
            for (int v = 0; v < 4; v++) acc[u][v] = fmaf(a[u], bb[v], acc[u][v]);
    }
    #pragma unroll
    for (int u = 0; u < 4; u++) {
        int r = rowbase + ty * 4 + u;
        #pragma unroll
        for (int v = 0; v < 4; v++) {
            int n = colbase + tx * 4 + v;
            g_xpre[r * G4 + n] = acc[u][v] + bih1[n] + bhh1[n];
        }
    }
}

// ---------------- LSTM recurrence: 2-CTA cluster per batch element ----------------
// rank owns gate rows [rank*256, rank*256+256), full weight row in registers.
// Per step: local matvec -> store gate to own + peer sh_g (double-buffered) ->
// cluster barrier -> both CTAs redundantly compute c/h update.
// which=1: LSTM1 (grid=2*BB, reads g_xpre, writes g_h1out)
// which=2: LSTM2 (grid=2, reads g_xpre2, writes g_dvec+8*HH)
__global__ __launch_bounds__(256, 1) __cluster_dims__(2, 1, 1)
void k_lstm_cl(const float* __restrict__ Whh, int steps, int which) {
    __shared__ __align__(16) float sh_h[HH];
    __shared__ float sh_c[HH];
    __shared__ __align__(16) float sh_g[2][G4];
    int tid = threadIdx.x;
    int rank = (int)(blockIdx.x & 1);
    int b = (int)(blockIdx.x >> 1);
    int n = rank * 256 + tid;

    // one-time: full weight row into registers (L2-broadcast across clusters)
    float4 wr[32];
    const float4* w4 = (const float4*)(Whh + n * HH);
    #pragma unroll
    for (int q = 0; q < 32; q++) wr[q] = __ldg(&w4[q]);

    if (tid < HH) { sh_h[tid] = 0.f; sh_c[tid] = 0.f; }

    // peer addresses of my gate slots in both buffers
    uint32_t l0 = (uint32_t)__cvta_generic_to_shared(&sh_g[0][n]);
    uint32_t l1 = (uint32_t)__cvta_generic_to_shared(&sh_g[1][n]);
    uint32_t peer = 1u ^ (uint32_t)rank;
    uint32_t r0, r1;
    asm("mapa.shared::cluster.u32 %0, %1, %2;" : "=r"(r0) : "r"(l0), "r"(peer));
    asm("mapa.shared::cluster.u32 %0, %1, %2;" : "=r"(r1) : "r"(l1), "r"(peer));
    __syncthreads();
    asm volatile("barrier.cluster.arrive.aligned;" ::: "memory");
    asm volatile("barrier.cluster.wait.aligned;" ::: "memory");

    const float4* h4 = (const float4*)sh_h;
    for (int s = 0; s < steps; s++) {
        int buf = s & 1;
        float acc = (which == 1) ? g_xpre[(s * BB + b) * G4 + n]
                                 : g_xpre2[s * G4 + n];
        float a0 = 0.f, a1 = 0.f, a2 = 0.f, a3 = 0.f;
        #pragma unroll
        for (int q = 0; q < 32; q++) {
            float4 h = h4[q];
            a0 = fmaf(wr[q].x, h.x, a0); a1 = fmaf(wr[q].y, h.y, a1);
            a2 = fmaf(wr[q].z, h.z, a2); a3 = fmaf(wr[q].w, h.w, a3);
        }
        float v = acc + ((a0 + a1) + (a2 + a3));
        sh_g[buf][n] = v;
        uint32_t ra = buf ? r1 : r0;
        asm volatile("st.shared::cluster.f32 [%0], %1;" :: "r"(ra), "f"(v) : "memory");
        asm volatile("barrier.cluster.arrive.aligned;" ::: "memory");
        asm volatile("barrier.cluster.wait.aligned;" ::: "memory");
        if (tid < HH) {
            float gi = sh_g[buf][tid], gf = sh_g[buf][HH + tid];
            float gg = sh_g[buf][2 * HH + tid], go = sh_g[buf][3 * HH + tid];
            float c = sigf(gf) * sh_c[tid] + sigf(gi) * tanhf(gg);
            sh_c[tid] = c;
            sh_h[tid] = sigf(go) * tanhf(c);
        }
        __syncthreads();
    }
    if (rank == 0 && tid < HH) {
        if (which == 1) g_h1out[b * HH + tid] = sh_h[tid];
        else            g_dvec[8 * HH + tid] = sh_h[tid];
    }
}

// ---------------- LSTM2 input GEMM: xpre2[s, n] = h1out[s,:] @ Wih2[n,:] + biases ----------------
__global__ __launch_bounds__(128) void k_xpre2(const float* __restrict__ Wih2,
                                               const float* __restrict__ bih2,
                                               const float* __restrict__ bhh2) {
    __shared__ float hh[BB * HH];
    int tid = threadIdx.x;
    for (int idx = tid; idx < BB * HH; idx += 128) hh[idx] = g_h1out[idx];
    __syncthreads();
    int n = blockIdx.x * 128 + tid;
    float4 wreg[32];
    const float4* w4 = (const float4*)(Wih2 + n * HH);
    #pragma unroll
    for (int kk = 0; kk < 32; kk++) wreg[kk] = __ldg(&w4[kk]);
    float bias = bih2[n] + bhh2[n];
    for (int s = 0; s < BB; s++) {
        const float4* h4 = (const float4*)(hh + s * HH);
        float a0 = 0.f, a1 = 0.f, a2 = 0.f, a3 = 0.f;
        #pragma unroll
        for (int kk = 0; kk < 32; kk++) {
            float4 h = h4[kk];
            a0 = fmaf(wreg[kk].x, h.x, a0); a1 = fmaf(wreg[kk].y, h.y, a1);
            a2 = fmaf(wreg[kk].z, h.z, a2); a3 = fmaf(wreg[kk].w, h.w, a3);
        }
        g_xpre2[s * G4 + n] = bias + ((a0 + a1) + (a2 + a3));
    }
}

// ---------------- MLP head: fuse m1_w @ m2_w (no nonlinearity in head) ----------------
__global__ void k_fw(const float* __restrict__ m1w, const float* __restrict__ m2w) {
    int i = blockIdx.x;
    float s = 0.f;
    for (int j = threadIdx.x; j < 576; j += 64) s += m1w[i * 576 + j] * m2w[j];
    #pragma unroll
    for (int off = 16; off > 0; off >>= 1) s += __shfl_down_sync(0xffffffffu, s, off);
    __shared__ float sm[2];
    if ((threadIdx.x & 31) == 0) sm[threadIdx.x >> 5] = s;
    __syncthreads();
    if (threadIdx.x == 0) g_fw[i] = sm[0] + sm[1];
}

__global__ void k_final(const float* __restrict__ m1b, const float* __restrict__ m2w,
                        const float* __restrict__ m2b, float* __restrict__ out) {
    __shared__ float red[512];
    float s = 0.f;
    for (int i = threadIdx.x; i < 9 * HH; i += 512) s += g_dvec[i] * g_fw[i];
    for (int j = threadIdx.x; j < 576; j += 512) s += m1b[j] * m2w[j];
    red[threadIdx.x] = s;
    __syncthreads();
    for (int st = 256; st > 0; st >>= 1) {
        if (threadIdx.x < st) red[threadIdx.x] += red[threadIdx.x + st];
        __syncthreads();
    }
    if (threadIdx.x == 0) out[0] = red[0] + m2b[0];
}

// ---------------- launch ----------------
extern "C" void kernel_launch(void* const* d_in, const int* in_sizes, int n_in,
                              void* d_out, int out_size) {
    const float* data0 = (const float*)d_in[0];
    const float* data1 = (const float*)d_in[1];
    const int*   ei    = (const int*)d_in[2];
    const float* W1   = (const float*)d_in[3];
    const float* b1   = (const float*)d_in[4];
    const float* W2   = (const float*)d_in[5];
    const float* b2   = (const float*)d_in[6];
    const float* Wih1 = (const float*)d_in[7];
    const float* Whh1 = (const float*)d_in[8];
    const float* bih1 = (const float*)d_in[9];
    const float* bhh1 = (const float*)d_in[10];
    const float* Wih2 = (const float*)d_in[11];
    const float* Whh2 = (const float*)d_in[12];
    const float* bih2 = (const float*)d_in[13];
    const float* bhh2 = (const float*)d_in[14];
    const float* m1w  = (const float*)d_in[15];
    const float* m1b  = (const float*)d_in[16];
    const float* m2w  = (const float*)d_in[17];
    const float* m2b  = (const float*)d_in[18];
    float* out = (float*)d_out;

    k_zero<<<(MAXSLOTS * HH + 255) / 256, 256>>>();
    k_scan1<<<(EE + 255) / 256, 256>>>(ei);
    k_dedupe<<<1, MAXT>>>();
    k_scan2<<<(EE + 255) / 256, 256>>>(ei);
    k_l1edge<<<512, HH>>>(data1, W1);
    k_l1self<<<128, HH>>>(data1, W1, b1);
    k_xw2<<<128, HH>>>(W2);
    k_l2tgt<<<8, HH>>>(b2);
    k_xpre<<<dim3(100, 8), 256>>>(data0, Wih1, bih1, bhh1);
    k_lstm_cl<<<2 * BB, 256>>>(Whh1, TT, 1);
    k_xpre2<<<4, 128>>>(Wih2, bih2, bhh2);
    k_lstm_cl<<<2, 256>>>(Whh2, BB, 2);
    k_fw<<<1152, 64>>>(m1w, m2w);
    k_final<<<1, 512>>>(m1b, m2w, m2b, out);
}

// round 6
// speedup vs baseline: 7.0231x; 1.0827x over previous
#include <cuda_runtime.h>
#include <math.h>
#include <stdint.h>

#define NN 100000
#define EE 800000
#define HH 128
#define G4 512
#define TT 200
#define BB 32
#define INQ 64
#define MAXT 1024
#define MAXSLOTS (MAXT + 8)
#define MAXL1 131072

// ---------------- device scratch (no allocs allowed) ----------------
__device__ float g_deg[NN];
__device__ int   g_flag[NN];
__device__ int   g_cnt[4];          // 0=slotCount 1=tgtEdgeCount 2=l1EdgeCount
__device__ int   g_tgt_src[MAXT];
__device__ int   g_tgt_t[MAXT];
__device__ int   g_tgt_slot[MAXT];
__device__ int   g_nodeOfSlot[MAXSLOTS];
__device__ int   g_l1_src[MAXL1];
__device__ int   g_l1_slot[MAXL1];
__device__ float g_xagg[MAXSLOTS * HH];  // layer-1 aggregated raw features
__device__ float g_h1[MAXSLOTS * HH];    // layer-1 output per slot
__device__ float g_hagg[8 * HH];         // layer-2 aggregated h1 at targets
__device__ float g_dvec[9 * HH];
__device__ float g_fw[9 * HH];
__device__ float g_xpre[TT * BB * G4];   // LSTM1 input gates (x-part + biases)
__device__ float g_h1out[BB * HH];       // LSTM1 final hidden
__device__ float g_xpre2[BB * G4];       // LSTM2 input gates

__device__ __forceinline__ float sigf(float x) { return 1.f / (1.f + expf(-x)); }

// ---------------- zero scratch ----------------
__global__ void k_zero() {
    int i = blockIdx.x * 256 + threadIdx.x;
    if (i < NN) { g_deg[i] = 0.f; g_flag[i] = 0; }
    if (i < MAXSLOTS * HH) g_xagg[i] = 0.f;
    if (i < 8 * HH) g_hagg[i] = 0.f;
    if (i < 4) g_cnt[i] = 0;
}

// ---------------- edge pass 1: degree histogram + edges into targets ----------------
__global__ void k_scan1(const int* __restrict__ ei) {
    int e = blockIdx.x * 256 + threadIdx.x;
    if (e >= EE) return;
    int d = ei[EE + e];
    atomicAdd(&g_deg[d], 1.0f);
    if (d <= 7000 && (d % 1000) == 0) {   // TARGET = {0,1000,...,7000}
        int ti = d / 1000;
        int p = atomicAdd(&g_cnt[1], 1);
        if (p < MAXT) { g_tgt_src[p] = ei[e]; g_tgt_t[p] = ti; }
    }
}

// ---------------- dedupe target-edge sources into slots; slots 0..7 = targets ----------------
__global__ void k_dedupe() {
    __shared__ int s_src[MAXT];
    __shared__ int s_first[MAXT];
    __shared__ int s_slot[MAXT];
    int i = threadIdx.x;
    int nT = g_cnt[1]; if (nT > MAXT) nT = MAXT;
    if (i < 8) { g_flag[i * 1000] = i + 1; g_nodeOfSlot[i] = i * 1000; }
    int s = (i < nT) ? g_tgt_src[i] : -1;
    s_src[i] = s;
    __syncthreads();
    int slot = -1, first = 0;
    if (i < nT) {
        #pragma unroll
        for (int k = 0; k < 8; k++) if (s == k * 1000) slot = k;
        if (slot < 0) {
            first = 1;
            for (int j = 0; j < i; j++) if (s_src[j] == s) { first = 0; break; }
        }
    }
    s_first[i] = (i < nT && slot < 0) ? first : 0;
    s_slot[i] = slot;
    __syncthreads();
    if (i < nT && slot < 0) {
        if (first) {
            int rank = 0;
            for (int j = 0; j < i; j++) rank += s_first[j];
            s_slot[i] = 8 + rank;
        } else {
            int j = 0; while (s_src[j] != s) j++;
            int rj = 0;
            for (int q = 0; q < j; q++) rj += s_first[q];
            s_slot[i] = 8 + rj;
        }
    }
    __syncthreads();
    if (i < nT) {
        g_tgt_slot[i] = s_slot[i];
        if (s_first[i]) { g_nodeOfSlot[s_slot[i]] = s_src[i]; g_flag[s_src[i]] = s_slot[i] + 1; }
    }
    if (i == 0) {
        int tot = 0;
        for (int j = 0; j < nT; j++) tot += s_first[j];
        g_cnt[0] = 8 + tot;
    }
}

// ---------------- edge pass 2: edges whose dst is in the 1-hop set ----------------
__global__ void k_scan2(const int* __restrict__ ei) {
    int e = blockIdx.x * 256 + threadIdx.x;
    if (e >= EE) return;
    int d = ei[EE + e];
    int f = g_flag[d];
    if (f > 0) {
        int p = atomicAdd(&g_cnt[2], 1);
        if (p < MAXL1) { g_l1_src[p] = ei[e]; g_l1_slot[p] = f - 1; }
    }
}

// ---------------- GCN layer 1: aggregate RAW features per slot (linearity fold) ----------------
__global__ void k_l1agg(const float* __restrict__ x) {
    int cnt = g_cnt[2]; if (cnt > MAXL1) cnt = MAXL1;
    for (int idx = blockIdx.x; idx < cnt; idx += gridDim.x) {
        int src = g_l1_src[idx], slot = g_l1_slot[idx];
        int dn = g_nodeOfSlot[slot];
        float norm = rsqrtf(g_deg[src] + 1.f) * rsqrtf(g_deg[dn] + 1.f);
        atomicAdd(&g_xagg[slot * HH + threadIdx.x], x[src * HH + threadIdx.x] * norm);
    }
}

// ---------------- GCN layer 1: (agg + self) @ W1 + b1, relu -> g_h1 ----------------
__global__ void k_l1mat(const float* __restrict__ x, const float* __restrict__ W1,
                        const float* __restrict__ b1) {
    __shared__ float xs[HH];
    int nslots = g_cnt[0];
    for (int slot = blockIdx.x; slot < nslots; slot += gridDim.x) {
        int node = g_nodeOfSlot[slot];
        float rs = rsqrtf(g_deg[node] + 1.f);
        float di2 = rs * rs;
        __syncthreads();
        xs[threadIdx.x] = g_xagg[slot * HH + threadIdx.x] + x[node * HH + threadIdx.x] * di2;
        __syncthreads();
        float acc = 0.f;
        #pragma unroll 8
        for (int k = 0; k < HH; k++) acc += xs[k] * W1[k * HH + threadIdx.x];
        g_h1[slot * HH + threadIdx.x] = fmaxf(acc + b1[threadIdx.x], 0.f);
    }
}

// ---------------- GCN layer 2: aggregate h1 at the 8 targets (linearity fold) ----------------
__global__ void k_l2agg() {
    int cnt = g_cnt[1]; if (cnt > MAXT) cnt = MAXT;
    for (int i = blockIdx.x; i < cnt; i += gridDim.x) {
        int t = g_tgt_t[i], s = g_tgt_src[i], slot = g_tgt_slot[i];
        int tn = t * 1000;
        float norm = rsqrtf(g_deg[s] + 1.f) * rsqrtf(g_deg[tn] + 1.f);
        atomicAdd(&g_hagg[t * HH + threadIdx.x], g_h1[slot * HH + threadIdx.x] * norm);
    }
}

// ---------------- GCN layer 2: (agg + self) @ W2 + b2, relu -> g_dvec[0:1024] ----------------
__global__ void k_l2mat(const float* __restrict__ W2, const float* __restrict__ b2) {
    __shared__ float hs[HH];
    int t = blockIdx.x, o = threadIdx.x;
    int tn = t * 1000;
    float rs = rsqrtf(g_deg[tn] + 1.f);
    float di2 = rs * rs;
    hs[o] = g_hagg[t * HH + o] + g_h1[t * HH + o] * di2;   // slot t == target t
    __syncthreads();
    float acc = 0.f;
    #pragma unroll 8
    for (int k = 0; k < HH; k++) acc += hs[k] * W2[k * HH + o];
    g_dvec[t * HH + o] = fmaxf(acc + b2[o], 0.f);
}

// ---------------- LSTM1 input GEMM: xpre[t*32+b, n] = data0[b,t,:] @ Wih1[n,:] + bih1+bhh1 ----------------
__global__ __launch_bounds__(256) void k_xpre(const float* __restrict__ data0,
                                              const float* __restrict__ Wih1,
                                              const float* __restrict__ bih1,
                                              const float* __restrict__ bhh1) {
    __shared__ float xs[64][65];
    __shared__ float ws[64][65];   // ws[k][j]
    int rowbase = blockIdx.x * 64;
    int colbase = blockIdx.y * 64;
    int tid = threadIdx.x;
    for (int idx = tid; idx < 64 * 64; idx += 256) {
        int i = idx >> 6, k = idx & 63;
        int r = rowbase + i, b = r & 31, t = r >> 5;
        xs[i][k] = data0[(b * TT + t) * INQ + k];
    }
    for (int idx = tid; idx < 64 * 64; idx += 256) {
        int j = idx >> 6, k = idx & 63;
        ws[k][j] = Wih1[(colbase + j) * INQ + k];
    }
    __syncthreads();
    int tx = tid & 15, ty = tid >> 4;
    float acc[4][4] = {};
    #pragma unroll 8
    for (int k = 0; k < 64; k++) {
        float a[4], bb[4];
        #pragma unroll
        for (int u = 0; u < 4; u++) a[u] = xs[ty * 4 + u][k];
        #pragma unroll
        for (int v = 0; v < 4; v++) bb[v] = ws[k][tx * 4 + v];
        #pragma unroll
        for (int u = 0; u < 4; u++)
            #pragma unroll
            for (int v = 0; v < 4; v++) acc[u][v] = fmaf(a[u], bb[v], acc[u][v]);
    }
    #pragma unroll
    for (int u = 0; u < 4; u++) {
        int r = rowbase + ty * 4 + u;
        #pragma unroll
        for (int v = 0; v < 4; v++) {
            int n = colbase + tx * 4 + v;
            g_xpre[r * G4 + n] = acc[u][v] + bih1[n] + bhh1[n];
        }
    }
}

// ---------------- LSTM recurrence: 2-CTA cluster, mbarrier handshake per step ----------------
#define MBAR_WAIT_CL(addr, parity) do {                                            \
    asm volatile("{\n\t.reg .pred P;\n\t"                                          \
        "WL_%=:\n\t"                                                               \
        "mbarrier.try_wait.parity.acquire.cluster.shared::cta.b64 P, [%0], %1;\n\t"\
        "@P bra.uni WD_%=;\n\t"                                                    \
        "bra.uni WL_%=;\n\t"                                                       \
        "WD_%=:\n\t}"                                                              \
        :: "r"(addr), "r"(parity) : "memory");                                     \
} while (0)

__global__ __launch_bounds__(256, 1) __cluster_dims__(2, 1, 1)
void k_lstm_cl(const float* __restrict__ Whh, int steps, int which) {
    __shared__ __align__(16) float sh_h[HH];
    __shared__ float sh_c[HH];
    __shared__ __align__(16) float sh_g[2][G4];
    __shared__ __align__(8) unsigned long long smbar[2];
    int tid = threadIdx.x;
    int rank = (int)(blockIdx.x & 1);
    int b = (int)(blockIdx.x >> 1);
    int n = rank * 256 + tid;

    // one-time: full weight row into registers (L2-broadcast across clusters)
    float4 wr[32];
    const float4* w4 = (const float4*)(Whh + n * HH);
    #pragma unroll
    for (int q = 0; q < 32; q++) wr[q] = __ldg(&w4[q]);

    if (tid < HH) { sh_h[tid] = 0.f; sh_c[tid] = 0.f; }
    if (tid == 0) {
        uint32_t b0 = (uint32_t)__cvta_generic_to_shared(&smbar[0]);
        uint32_t b1a = (uint32_t)__cvta_generic_to_shared(&smbar[1]);
        asm volatile("mbarrier.init.shared.b64 [%0], %1;" :: "r"(b0), "r"(256u));
        asm volatile("mbarrier.init.shared.b64 [%0], %1;" :: "r"(b1a), "r"(256u));
    }

    // peer addresses (gate slots + peer's mbarriers)
    uint32_t lg0 = (uint32_t)__cvta_generic_to_shared(&sh_g[0][n]);
    uint32_t lg1 = (uint32_t)__cvta_generic_to_shared(&sh_g[1][n]);
    uint32_t lb0 = (uint32_t)__cvta_generic_to_shared(&smbar[0]);
    uint32_t lb1 = (uint32_t)__cvta_generic_to_shared(&smbar[1]);
    uint32_t peer = 1u ^ (uint32_t)rank;
    uint32_t rg0, rg1, rb0, rb1;
    asm("mapa.shared::cluster.u32 %0, %1, %2;" : "=r"(rg0) : "r"(lg0), "r"(peer));
    asm("mapa.shared::cluster.u32 %0, %1, %2;" : "=r"(rg1) : "r"(lg1), "r"(peer));
    asm("mapa.shared::cluster.u32 %0, %1, %2;" : "=r"(rb0) : "r"(lb0), "r"(peer));
    asm("mapa.shared::cluster.u32 %0, %1, %2;" : "=r"(rb1) : "r"(lb1), "r"(peer));
    __syncthreads();
    asm volatile("barrier.cluster.arrive.aligned;" ::: "memory");
    asm volatile("barrier.cluster.wait.aligned;" ::: "memory");

    const float4* h4 = (const float4*)sh_h;
    int ph0 = 0, ph1 = 0;
    for (int s = 0; s < steps; s++) {
        int buf = s & 1;
        float acc = (which == 1) ? g_xpre[(s * BB + b) * G4 + n]
                                 : g_xpre2[s * G4 + n];
        float a0 = 0.f, a1 = 0.f, a2 = 0.f, a3 = 0.f;
        #pragma unroll
        for (int q = 0; q < 32; q++) {
            float4 h = h4[q];
            a0 = fmaf(wr[q].x, h.x, a0); a1 = fmaf(wr[q].y, h.y, a1);
            a2 = fmaf(wr[q].z, h.z, a2); a3 = fmaf(wr[q].w, h.w, a3);
        }
        float v = acc + ((a0 + a1) + (a2 + a3));
        sh_g[buf][n] = v;
        uint32_t rg = buf ? rg1 : rg0;
        uint32_t rb = buf ? rb1 : rb0;
        asm volatile("st.shared::cluster.f32 [%0], %1;" :: "r"(rg), "f"(v) : "memory");
        asm volatile("mbarrier.arrive.release.cluster.shared::cluster.b64 _, [%0];"
                     :: "r"(rb) : "memory");
        // wait for peer's 256 arrivals on my barrier for this buffer
        if (buf) { MBAR_WAIT_CL(lb1, ph1); ph1 ^= 1; }
        else     { MBAR_WAIT_CL(lb0, ph0); ph0 ^= 1; }
        __syncthreads();   // local gate writes + uniform step alignment
        if (tid < HH) {
            float gi = sh_g[buf][tid], gf = sh_g[buf][HH + tid];
            float gg = sh_g[buf][2 * HH + tid], go = sh_g[buf][3 * HH + tid];
            float c = sigf(gf) * sh_c[tid] + sigf(gi) * tanhf(gg);
            sh_c[tid] = c;
            sh_h[tid] = sigf(go) * tanhf(c);
        }
        __syncthreads();
    }
    if (rank == 0 && tid < HH) {
        if (which == 1) g_h1out[b * HH + tid] = sh_h[tid];
        else            g_dvec[8 * HH + tid] = sh_h[tid];
    }
}

// ---------------- LSTM2 input GEMM: xpre2[s, n] = h1out[s,:] @ Wih2[n,:] + biases ----------------
__global__ __launch_bounds__(128) void k_xpre2(const float* __restrict__ Wih2,
                                               const float* __restrict__ bih2,
                                               const float* __restrict__ bhh2) {
    __shared__ float hh[BB * HH];
    int tid = threadIdx.x;
    for (int idx = tid; idx < BB * HH; idx += 128) hh[idx] = g_h1out[idx];
    __syncthreads();
    int n = blockIdx.x * 128 + tid;
    float4 wreg[32];
    const float4* w4 = (const float4*)(Wih2 + n * HH);
    #pragma unroll
    for (int kk = 0; kk < 32; kk++) wreg[kk] = __ldg(&w4[kk]);
    float bias = bih2[n] + bhh2[n];
    for (int s = 0; s < BB; s++) {
        const float4* h4 = (const float4*)(hh + s * HH);
        float a0 = 0.f, a1 = 0.f, a2 = 0.f, a3 = 0.f;
        #pragma unroll
        for (int kk = 0; kk < 32; kk++) {
            float4 h = h4[kk];
            a0 = fmaf(wreg[kk].x, h.x, a0); a1 = fmaf(wreg[kk].y, h.y, a1);
            a2 = fmaf(wreg[kk].z, h.z, a2); a3 = fmaf(wreg[kk].w, h.w, a3);
        }
        g_xpre2[s * G4 + n] = bias + ((a0 + a1) + (a2 + a3));
    }
}

// ---------------- MLP head: fuse m1_w @ m2_w (no nonlinearity in head) ----------------
__global__ void k_fw(const float* __restrict__ m1w, const float* __restrict__ m2w) {
    int i = blockIdx.x;
    float s = 0.f;
    for (int j = threadIdx.x; j < 576; j += 64) s += m1w[i * 576 + j] * m2w[j];
    #pragma unroll
    for (int off = 16; off > 0; off >>= 1) s += __shfl_down_sync(0xffffffffu, s, off);
    __shared__ float sm[2];
    if ((threadIdx.x & 31) == 0) sm[threadIdx.x >> 5] = s;
    __syncthreads();
    if (threadIdx.x == 0) g_fw[i] = sm[0] + sm[1];
}

__global__ void k_final(const float* __restrict__ m1b, const float* __restrict__ m2w,
                        const float* __restrict__ m2b, float* __restrict__ out) {
    __shared__ float red[512];
    float s = 0.f;
    for (int i = threadIdx.x; i < 9 * HH; i += 512) s += g_dvec[i] * g_fw[i];
    for (int j = threadIdx.x; j < 576; j += 512) s += m1b[j] * m2w[j];
    red[threadIdx.x] = s;
    __syncthreads();
    for (int st = 256; st > 0; st >>= 1) {
        if (threadIdx.x < st) red[threadIdx.x] += red[threadIdx.x + st];
        __syncthreads();
    }
    if (threadIdx.x == 0) out[0] = red[0] + m2b[0];
}

// ---------------- launch ----------------
extern "C" void kernel_launch(void* const* d_in, const int* in_sizes, int n_in,
                              void* d_out, int out_size) {
    const float* data0 = (const float*)d_in[0];
    const float* data1 = (const float*)d_in[1];
    const int*   ei    = (const int*)d_in[2];
    const float* W1   = (const float*)d_in[3];
    const float* b1   = (const float*)d_in[4];
    const float* W2   = (const float*)d_in[5];
    const float* b2   = (const float*)d_in[6];
    const float* Wih1 = (const float*)d_in[7];
    const float* Whh1 = (const float*)d_in[8];
    const float* bih1 = (const float*)d_in[9];
    const float* bhh1 = (const float*)d_in[10];
    const float* Wih2 = (const float*)d_in[11];
    const float* Whh2 = (const float*)d_in[12];
    const float* bih2 = (const float*)d_in[13];
    const float* bhh2 = (const float*)d_in[14];
    const float* m1w  = (const float*)d_in[15];
    const float* m1b  = (const float*)d_in[16];
    const float* m2w  = (const float*)d_in[17];
    const float* m2b  = (const float*)d_in[18];
    float* out = (float*)d_out;

    static cudaStream_t s2 = nullptr;
    static cudaEvent_t evA = nullptr, evB = nullptr;
    if (!s2) {
        cudaStreamCreateWithFlags(&s2, cudaStreamNonBlocking);
        cudaEventCreateWithFlags(&evA, cudaEventDisableTiming);
        cudaEventCreateWithFlags(&evB, cudaEventDisableTiming);
    }

    // fork: GCN chain + head-weight fold run on s2, LSTM chain on default stream
    cudaEventRecord(evA, 0);
    cudaStreamWaitEvent(s2, evA, 0);

    k_zero<<<(MAXSLOTS * HH + 255) / 256, 256, 0, s2>>>();
    k_scan1<<<(EE + 255) / 256, 256, 0, s2>>>(ei);
    k_dedupe<<<1, MAXT, 0, s2>>>();
    k_scan2<<<(EE + 255) / 256, 256, 0, s2>>>(ei);
    k_l1agg<<<256, HH, 0, s2>>>(data1);
    k_l1mat<<<128, HH, 0, s2>>>(data1, W1, b1);
    k_l2agg<<<64, HH, 0, s2>>>();
    k_l2mat<<<8, HH, 0, s2>>>(W2, b2);
    k_fw<<<1152, 64, 0, s2>>>(m1w, m2w);

    k_xpre<<<dim3(100, 8), 256>>>(data0, Wih1, bih1, bhh1);
    k_lstm_cl<<<2 * BB, 256>>>(Whh1, TT, 1);
    k_xpre2<<<4, 128>>>(Wih2, bih2, bhh2);
    k_lstm_cl<<<2, 256>>>(Whh2, BB, 2);

    // join
    cudaEventRecord(evB, s2);
    cudaStreamWaitEvent(0, evB, 0);
    k_final<<<1, 512>>>(m1b, m2w, m2b, out);
}

// round 7
// speedup vs baseline: 7.4441x; 1.0599x over previous
#include <cuda_runtime.h>
#include <math.h>
#include <stdint.h>

#define NN 100000
#define EE 800000
#define HH 128
#define G4 512
#define TT 200
#define BB 32
#define INQ 64
#define MAXT 1024
#define MAXSLOTS (MAXT + 8)
#define MAXL1 131072

// ---------------- device scratch (no allocs allowed) ----------------
__device__ float g_deg[NN];
__device__ int   g_flag[NN];
__device__ int   g_cnt[4];          // 0=slotCount 1=tgtEdgeCount 2=l1EdgeCount
__device__ int   g_tgt_src[MAXT];
__device__ int   g_tgt_t[MAXT];
__device__ int   g_tgt_slot[MAXT];
__device__ int   g_nodeOfSlot[MAXSLOTS];
__device__ int   g_l1_src[MAXL1];
__device__ int   g_l1_slot[MAXL1];
__device__ float g_xagg[MAXSLOTS * HH];  // layer-1 aggregated raw features
__device__ float g_h1[MAXSLOTS * HH];    // layer-1 output per slot
__device__ float g_hagg[8 * HH];         // layer-2 aggregated h1 at targets
__device__ float g_dvec[9 * HH];
__device__ float g_fw[9 * HH];
__device__ float g_xpre[TT * BB * G4];   // LSTM1 input gates (x-part + biases)
__device__ float g_h1out[BB * HH];       // LSTM1 final hidden
__device__ float g_xpre2[BB * G4];       // LSTM2 input gates

__device__ __forceinline__ float fsig(float x) {
    return __fdividef(1.f, 1.f + __expf(-x));
}
__device__ __forceinline__ float ftanh(float x) {
    return __fdividef(2.f, 1.f + __expf(-2.f * x)) - 1.f;
}

// ---------------- zero scratch ----------------
__global__ void k_zero() {
    int i = blockIdx.x * 256 + threadIdx.x;
    if (i < NN) { g_deg[i] = 0.f; g_flag[i] = 0; }
    if (i < MAXSLOTS * HH) g_xagg[i] = 0.f;
    if (i < 8 * HH) g_hagg[i] = 0.f;
    if (i < 4) g_cnt[i] = 0;
}

// ---------------- edge pass 1: degree histogram + edges into targets ----------------
__global__ void k_scan1(const int* __restrict__ ei) {
    int e = blockIdx.x * 256 + threadIdx.x;
    if (e >= EE) return;
    int d = ei[EE + e];
    atomicAdd(&g_deg[d], 1.0f);
    if (d <= 7000 && (d % 1000) == 0) {   // TARGET = {0,1000,...,7000}
        int ti = d / 1000;
        int p = atomicAdd(&g_cnt[1], 1);
        if (p < MAXT) { g_tgt_src[p] = ei[e]; g_tgt_t[p] = ti; }
    }
}

// ---------------- dedupe target-edge sources into slots; slots 0..7 = targets ----------------
__global__ void k_dedupe() {
    __shared__ int s_src[MAXT];
    __shared__ int s_first[MAXT];
    __shared__ int s_slot[MAXT];
    int i = threadIdx.x;
    int nT = g_cnt[1]; if (nT > MAXT) nT = MAXT;
    if (i < 8) { g_flag[i * 1000] = i + 1; g_nodeOfSlot[i] = i * 1000; }
    int s = (i < nT) ? g_tgt_src[i] : -1;
    s_src[i] = s;
    __syncthreads();
    int slot = -1, first = 0;
    if (i < nT) {
        #pragma unroll
        for (int k = 0; k < 8; k++) if (s == k * 1000) slot = k;
        if (slot < 0) {
            first = 1;
            for (int j = 0; j < i; j++) if (s_src[j] == s) { first = 0; break; }
        }
    }
    s_first[i] = (i < nT && slot < 0) ? first : 0;
    s_slot[i] = slot;
    __syncthreads();
    if (i < nT && slot < 0) {
        if (first) {
            int rank = 0;
            for (int j = 0; j < i; j++) rank += s_first[j];
            s_slot[i] = 8 + rank;
        } else {
            int j = 0; while (s_src[j] != s) j++;
            int rj = 0;
            for (int q = 0; q < j; q++) rj += s_first[q];
            s_slot[i] = 8 + rj;
        }
    }
    __syncthreads();
    if (i < nT) {
        g_tgt_slot[i] = s_slot[i];
        if (s_first[i]) { g_nodeOfSlot[s_slot[i]] = s_src[i]; g_flag[s_src[i]] = s_slot[i] + 1; }
    }
    if (i == 0) {
        int tot = 0;
        for (int j = 0; j < nT; j++) tot += s_first[j];
        g_cnt[0] = 8 + tot;
    }
}

// ---------------- edge pass 2: edges whose dst is in the 1-hop set ----------------
__global__ void k_scan2(const int* __restrict__ ei) {
    int e = blockIdx.x * 256 + threadIdx.x;
    if (e >= EE) return;
    int d = ei[EE + e];
    int f = g_flag[d];
    if (f > 0) {
        int p = atomicAdd(&g_cnt[2], 1);
        if (p < MAXL1) { g_l1_src[p] = ei[e]; g_l1_slot[p] = f - 1; }
    }
}

// ---------------- GCN layer 1: aggregate RAW features per slot (linearity fold) ----------------
__global__ void k_l1agg(const float* __restrict__ x) {
    int cnt = g_cnt[2]; if (cnt > MAXL1) cnt = MAXL1;
    for (int idx = blockIdx.x; idx < cnt; idx += gridDim.x) {
        int src = g_l1_src[idx], slot = g_l1_slot[idx];
        int dn = g_nodeOfSlot[slot];
        float norm = rsqrtf(g_deg[src] + 1.f) * rsqrtf(g_deg[dn] + 1.f);
        atomicAdd(&g_xagg[slot * HH + threadIdx.x], x[src * HH + threadIdx.x] * norm);
    }
}

// ---------------- GCN layer 1: (agg + self) @ W1 + b1, relu -> g_h1 ----------------
__global__ void k_l1mat(const float* __restrict__ x, const float* __restrict__ W1,
                        const float* __restrict__ b1) {
    __shared__ float xs[HH];
    int nslots = g_cnt[0];
    for (int slot = blockIdx.x; slot < nslots; slot += gridDim.x) {
        int node = g_nodeOfSlot[slot];
        float rs = rsqrtf(g_deg[node] + 1.f);
        float di2 = rs * rs;
        __syncthreads();
        xs[threadIdx.x] = g_xagg[slot * HH + threadIdx.x] + x[node * HH + threadIdx.x] * di2;
        __syncthreads();
        float acc = 0.f;
        #pragma unroll 8
        for (int k = 0; k < HH; k++) acc += xs[k] * W1[k * HH + threadIdx.x];
        g_h1[slot * HH + threadIdx.x] = fmaxf(acc + b1[threadIdx.x], 0.f);
    }
}

// ---------------- GCN layer 2: aggregate h1 at the 8 targets (linearity fold) ----------------
__global__ void k_l2agg() {
    int cnt = g_cnt[1]; if (cnt > MAXT) cnt = MAXT;
    for (int i = blockIdx.x; i < cnt; i += gridDim.x) {
        int t = g_tgt_t[i], s = g_tgt_src[i], slot = g_tgt_slot[i];
        int tn = t * 1000;
        float norm = rsqrtf(g_deg[s] + 1.f) * rsqrtf(g_deg[tn] + 1.f);
        atomicAdd(&g_hagg[t * HH + threadIdx.x], g_h1[slot * HH + threadIdx.x] * norm);
    }
}

// ---------------- GCN layer 2: (agg + self) @ W2 + b2, relu -> g_dvec[0:1024] ----------------
__global__ void k_l2mat(const float* __restrict__ W2, const float* __restrict__ b2) {
    __shared__ float hs[HH];
    int t = blockIdx.x, o = threadIdx.x;
    int tn = t * 1000;
    float rs = rsqrtf(g_deg[tn] + 1.f);
    float di2 = rs * rs;
    hs[o] = g_hagg[t * HH + o] + g_h1[t * HH + o] * di2;   // slot t == target t
    __syncthreads();
    float acc = 0.f;
    #pragma unroll 8
    for (int k = 0; k < HH; k++) acc += hs[k] * W2[k * HH + o];
    g_dvec[t * HH + o] = fmaxf(acc + b2[o], 0.f);
}

// ---------------- LSTM1 input GEMM: xpre[t*32+b, n] = data0[b,t,:] @ Wih1[n,:] + bih1+bhh1 ----------------
__global__ __launch_bounds__(256) void k_xpre(const float* __restrict__ data0,
                                              const float* __restrict__ Wih1,
                                              const float* __restrict__ bih1,
                                              const float* __restrict__ bhh1) {
    __shared__ float xs[64][65];
    __shared__ float ws[64][65];   // ws[k][j]
    int rowbase = blockIdx.x * 64;
    int colbase = blockIdx.y * 64;
    int tid = threadIdx.x;
    for (int idx = tid; idx < 64 * 64; idx += 256) {
        int i = idx >> 6, k = idx & 63;
        int r = rowbase + i, b = r & 31, t = r >> 5;
        xs[i][k] = data0[(b * TT + t) * INQ + k];
    }
    for (int idx = tid; idx < 64 * 64; idx += 256) {
        int j = idx >> 6, k = idx & 63;
        ws[k][j] = Wih1[(colbase + j) * INQ + k];
    }
    __syncthreads();
    int tx = tid & 15, ty = tid >> 4;
    float acc[4][4] = {};
    #pragma unroll 8
    for (int k = 0; k < 64; k++) {
        float a[4], bb[4];
        #pragma unroll
        for (int u = 0; u < 4; u++) a[u] = xs[ty * 4 + u][k];
        #pragma unroll
        for (int v = 0; v < 4; v++) bb[v] = ws[k][tx * 4 + v];
        #pragma unroll
        for (int u = 0; u < 4; u++)
            #pragma unroll
            for (int v = 0; v < 4; v++) acc[u][v] = fmaf(a[u], bb[v], acc[u][v]);
    }
    #pragma unroll
    for (int u = 0; u < 4; u++) {
        int r = rowbase + ty * 4 + u;
        #pragma unroll
        for (int v = 0; v < 4; v++) {
            int n = colbase + tx * 4 + v;
            g_xpre[r * G4 + n] = acc[u][v] + bih1[n] + bhh1[n];
        }
    }
}

// ---------------- LSTM recurrence: 2-CTA cluster; CTA r owns ALL 4 gates for h[64r,64r+64) ----------
// Only the 64-float h-chunk crosses CTAs per step. Matvec uses packed fma.rn.f32x2.
#define MBAR_WAIT_CL(addr, parity) do {                                            \
    asm volatile("{\n\t.reg .pred P;\n\t"                                          \
        "WL_%=:\n\t"                                                               \
        "mbarrier.try_wait.parity.acquire.cluster.shared::cta.b64 P, [%0], %1;\n\t"\
        "@P bra.uni WD_%=;\n\t"                                                    \
        "bra.uni WL_%=;\n\t"                                                       \
        "WD_%=:\n\t}"                                                              \
        :: "r"(addr), "r"(parity) : "memory");                                     \
} while (0)

__global__ __launch_bounds__(256, 1) __cluster_dims__(2, 1, 1)
void k_lstm_cl(const float* __restrict__ Whh, int steps, int which) {
    __shared__ __align__(16) float sh_h[2][HH];
    __shared__ float sh_gl[256];
    __shared__ __align__(8) unsigned long long smb[2];
    int tid = threadIdx.x;
    int rank = (int)(blockIdx.x & 1);
    int b = (int)(blockIdx.x >> 1);
    int gt = tid >> 6;            // gate type 0..3
    int m  = tid & 63;            // h-offset within my chunk
    int hidx = (rank << 6) + m;   // global h index my chunk covers
    int row  = gt * HH + hidx;    // gate row this thread computes

    // one-time: weight row packed into 64 b64 registers
    unsigned long long wq[64];
    {
        const float4* w4 = (const float4*)(Whh + row * HH);
        #pragma unroll
        for (int q = 0; q < 32; q++) {
            float4 w = __ldg(&w4[q]);
            asm("mov.b64 %0, {%1,%2};" : "=l"(wq[2 * q])     : "f"(w.x), "f"(w.y));
            asm("mov.b64 %0, {%1,%2};" : "=l"(wq[2 * q + 1]) : "f"(w.z), "f"(w.w));
        }
    }

    if (tid < HH) sh_h[0][tid] = 0.f;
    if (tid == 0) {
        uint32_t b0 = (uint32_t)__cvta_generic_to_shared(&smb[0]);
        uint32_t b1 = (uint32_t)__cvta_generic_to_shared(&smb[1]);
        asm volatile("mbarrier.init.shared.b64 [%0], %1;" :: "r"(b0), "r"(64u));
        asm volatile("mbarrier.init.shared.b64 [%0], %1;" :: "r"(b1), "r"(64u));
    }

    uint32_t sh_base = (uint32_t)__cvta_generic_to_shared(&sh_h[0][0]);
    uint32_t lb0 = (uint32_t)__cvta_generic_to_shared(&smb[0]);
    uint32_t lb1 = (uint32_t)__cvta_generic_to_shared(&smb[1]);
    uint32_t lh0 = (uint32_t)__cvta_generic_to_shared(&sh_h[0][hidx]);
    uint32_t lh1 = (uint32_t)__cvta_generic_to_shared(&sh_h[1][hidx]);
    uint32_t peer = 1u ^ (uint32_t)rank;
    uint32_t rh0, rh1, rb0, rb1;
    asm("mapa.shared::cluster.u32 %0, %1, %2;" : "=r"(rh0) : "r"(lh0), "r"(peer));
    asm("mapa.shared::cluster.u32 %0, %1, %2;" : "=r"(rh1) : "r"(lh1), "r"(peer));
    asm("mapa.shared::cluster.u32 %0, %1, %2;" : "=r"(rb0) : "r"(lb0), "r"(peer));
    asm("mapa.shared::cluster.u32 %0, %1, %2;" : "=r"(rb1) : "r"(lb1), "r"(peer));
    __syncthreads();
    asm volatile("barrier.cluster.arrive.aligned;" ::: "memory");
    asm volatile("barrier.cluster.wait.aligned;" ::: "memory");

    int ph0 = 0, ph1 = 0;
    float c = 0.f;
    float accn = (which == 1) ? g_xpre[b * G4 + row] : g_xpre2[row];
    for (int s = 0; s < steps; s++) {
        int buf = s & 1;
        if (s > 0) {
            if (buf) { MBAR_WAIT_CL(lb1, ph1); ph1 ^= 1; }
            else     { MBAR_WAIT_CL(lb0, ph0); ph0 ^= 1; }
        }
        float acc = accn;
        if (s + 1 < steps)
            accn = (which == 1) ? g_xpre[((s + 1) * BB + b) * G4 + row]
                                : g_xpre2[(s + 1) * G4 + row];

        // matvec over sh_h[buf] with packed f32x2 FMAs
        unsigned long long a0 = 0ull, a1 = 0ull, a2 = 0ull, a3 = 0ull;
        uint32_t hb = sh_base + ((uint32_t)buf << 9);
        #pragma unroll
        for (int q = 0; q < 32; q++) {
            unsigned long long h01, h23;
            asm volatile("ld.shared.v2.u64 {%0,%1}, [%2];"
                         : "=l"(h01), "=l"(h23) : "r"(hb + q * 16));
            if (q & 1) {
                asm("fma.rn.f32x2 %0, %1, %2, %0;" : "+l"(a2) : "l"(wq[2 * q]),     "l"(h01));
                asm("fma.rn.f32x2 %0, %1, %2, %0;" : "+l"(a3) : "l"(wq[2 * q + 1]), "l"(h23));
            } else {
                asm("fma.rn.f32x2 %0, %1, %2, %0;" : "+l"(a0) : "l"(wq[2 * q]),     "l"(h01));
                asm("fma.rn.f32x2 %0, %1, %2, %0;" : "+l"(a1) : "l"(wq[2 * q + 1]), "l"(h23));
            }
        }
        asm("add.rn.f32x2 %0, %0, %1;" : "+l"(a0) : "l"(a2));
        asm("add.rn.f32x2 %0, %0, %1;" : "+l"(a1) : "l"(a3));
        float x0, y0, x1, y1;
        asm("mov.b64 {%0,%1}, %2;" : "=f"(x0), "=f"(y0) : "l"(a0));
        asm("mov.b64 {%0,%1}, %2;" : "=f"(x1), "=f"(y1) : "l"(a1));
        sh_gl[tid] = acc + ((x0 + y0) + (x1 + y1));
        __syncthreads();

        if (tid < 64) {
            float gi = sh_gl[m], gf = sh_gl[64 + m];
            float gg = sh_gl[128 + m], go = sh_gl[192 + m];
            c = fsig(gf) * c + fsig(gi) * ftanh(gg);
            float h = fsig(go) * ftanh(c);
            if (s + 1 < steps) {
                int bn = (s + 1) & 1;
                sh_h[bn][hidx] = h;
                uint32_t rg = bn ? rh1 : rh0;
                uint32_t rb = bn ? rb1 : rb0;
                asm volatile("st.shared::cluster.f32 [%0], %1;" :: "r"(rg), "f"(h) : "memory");
                asm volatile("mbarrier.arrive.release.cluster.shared::cluster.b64 _, [%0];"
                             :: "r"(rb) : "memory");
            } else {
                if (which == 1) g_h1out[b * HH + hidx] = h;
                else            g_dvec[8 * HH + hidx] = h;
            }
        }
        __syncthreads();
    }
}

// ---------------- LSTM2 input GEMM: xpre2[s, n] = h1out[s,:] @ Wih2[n,:] + biases ----------------
__global__ __launch_bounds__(128) void k_xpre2(const float* __restrict__ Wih2,
                                               const float* __restrict__ bih2,
                                               const float* __restrict__ bhh2) {
    __shared__ float hh[BB * HH];
    int tid = threadIdx.x;
    for (int idx = tid; idx < BB * HH; idx += 128) hh[idx] = g_h1out[idx];
    __syncthreads();
    int n = blockIdx.x * 128 + tid;
    float4 wreg[32];
    const float4* w4 = (const float4*)(Wih2 + n * HH);
    #pragma unroll
    for (int kk = 0; kk < 32; kk++) wreg[kk] = __ldg(&w4[kk]);
    float bias = bih2[n] + bhh2[n];
    for (int s = 0; s < BB; s++) {
        const float4* h4 = (const float4*)(hh + s * HH);
        float a0 = 0.f, a1 = 0.f, a2 = 0.f, a3 = 0.f;
        #pragma unroll
        for (int kk = 0; kk < 32; kk++) {
            float4 h = h4[kk];
            a0 = fmaf(wreg[kk].x, h.x, a0); a1 = fmaf(wreg[kk].y, h.y, a1);
            a2 = fmaf(wreg[kk].z, h.z, a2); a3 = fmaf(wreg[kk].w, h.w, a3);
        }
        g_xpre2[s * G4 + n] = bias + ((a0 + a1) + (a2 + a3));
    }
}

// ---------------- MLP head: fuse m1_w @ m2_w (no nonlinearity in head) ----------------
__global__ void k_fw(const float* __restrict__ m1w, const float* __restrict__ m2w) {
    int i = blockIdx.x;
    float s = 0.f;
    for (int j = threadIdx.x; j < 576; j += 64) s += m1w[i * 576 + j] * m2w[j];
    #pragma unroll
    for (int off = 16; off > 0; off >>= 1) s += __shfl_down_sync(0xffffffffu, s, off);
    __shared__ float sm[2];
    if ((threadIdx.x & 31) == 0) sm[threadIdx.x >> 5] = s;
    __syncthreads();
    if (threadIdx.x == 0) g_fw[i] = sm[0] + sm[1];
}

__global__ void k_final(const float* __restrict__ m1b, const float* __restrict__ m2w,
                        const float* __restrict__ m2b, float* __restrict__ out) {
    __shared__ float red[512];
    float s = 0.f;
    for (int i = threadIdx.x; i < 9 * HH; i += 512) s += g_dvec[i] * g_fw[i];
    for (int j = threadIdx.x; j < 576; j += 512) s += m1b[j] * m2w[j];
    red[threadIdx.x] = s;
    __syncthreads();
    for (int st = 256; st > 0; st >>= 1) {
        if (threadIdx.x < st) red[threadIdx.x] += red[threadIdx.x + st];
        __syncthreads();
    }
    if (threadIdx.x == 0) out[0] = red[0] + m2b[0];
}

// ---------------- launch ----------------
extern "C" void kernel_launch(void* const* d_in, const int* in_sizes, int n_in,
                              void* d_out, int out_size) {
    const float* data0 = (const float*)d_in[0];
    const float* data1 = (const float*)d_in[1];
    const int*   ei    = (const int*)d_in[2];
    const float* W1   = (const float*)d_in[3];
    const float* b1   = (const float*)d_in[4];
    const float* W2   = (const float*)d_in[5];
    const float* b2   = (const float*)d_in[6];
    const float* Wih1 = (const float*)d_in[7];
    const float* Whh1 = (const float*)d_in[8];
    const float* bih1 = (const float*)d_in[9];
    const float* bhh1 = (const float*)d_in[10];
    const float* Wih2 = (const float*)d_in[11];
    const float* Whh2 = (const float*)d_in[12];
    const float* bih2 = (const float*)d_in[13];
    const float* bhh2 = (const float*)d_in[14];
    const float* m1w  = (const float*)d_in[15];
    const float* m1b  = (const float*)d_in[16];
    const float* m2w  = (const float*)d_in[17];
    const float* m2b  = (const float*)d_in[18];
    float* out = (float*)d_out;

    static cudaStream_t s2 = nullptr;
    static cudaEvent_t evA = nullptr, evB = nullptr;
    if (!s2) {
        cudaStreamCreateWithFlags(&s2, cudaStreamNonBlocking);
        cudaEventCreateWithFlags(&evA, cudaEventDisableTiming);
        cudaEventCreateWithFlags(&evB, cudaEventDisableTiming);
    }

    // fork: GCN chain + head-weight fold run on s2, LSTM chain on default stream
    cudaEventRecord(evA, 0);
    cudaStreamWaitEvent(s2, evA, 0);

    k_zero<<<(MAXSLOTS * HH + 255) / 256, 256, 0, s2>>>();
    k_scan1<<<(EE + 255) / 256, 256, 0, s2>>>(ei);
    k_dedupe<<<1, MAXT, 0, s2>>>();
    k_scan2<<<(EE + 255) / 256, 256, 0, s2>>>(ei);
    k_l1agg<<<256, HH, 0, s2>>>(data1);
    k_l1mat<<<128, HH, 0, s2>>>(data1, W1, b1);
    k_l2agg<<<64, HH, 0, s2>>>();
    k_l2mat<<<8, HH, 0, s2>>>(W2, b2);
    k_fw<<<1152, 64, 0, s2>>>(m1w, m2w);

    k_xpre<<<dim3(100, 8), 256>>>(data0, Wih1, bih1, bhh1);
    k_lstm_cl<<<2 * BB, 256>>>(Whh1, TT, 1);
    k_xpre2<<<4, 128>>>(Wih2, bih2, bhh2);
    k_lstm_cl<<<2, 256>>>(Whh2, BB, 2);

    // join
    cudaEventRecord(evB, s2);
    cudaStreamWaitEvent(0, evB, 0);
    k_final<<<1, 512>>>(m1b, m2w, m2b, out);
}

// round 8
// speedup vs baseline: 7.5193x; 1.0101x over previous
#include <cuda_runtime.h>
#include <math.h>
#include <stdint.h>

#define NN 100000
#define EE 800000
#define HH 128
#define G4 512
#define TT 200
#define BB 32
#define INQ 64
#define MAXT 1024
#define MAXSLOTS (MAXT + 8)
#define MAXL1 131072

// ---------------- device scratch (no allocs allowed) ----------------
__device__ float g_deg[NN];
__device__ int   g_flag[NN];
__device__ int   g_cnt[4];          // 0=slotCount 1=tgtEdgeCount 2=l1EdgeCount
__device__ int   g_tgt_src[MAXT];
__device__ int   g_tgt_t[MAXT];
__device__ int   g_tgt_slot[MAXT];
__device__ int   g_nodeOfSlot[MAXSLOTS];
__device__ int   g_l1_src[MAXL1];
__device__ int   g_l1_slot[MAXL1];
__device__ float g_xagg[MAXSLOTS * HH];  // layer-1 aggregated raw features
__device__ float g_h1[MAXSLOTS * HH];    // layer-1 output per slot
__device__ float g_hagg[8 * HH];         // layer-2 aggregated h1 at targets
__device__ float g_dvec[9 * HH];
__device__ float g_fw[9 * HH];
__device__ float g_xpre[TT * BB * G4];   // LSTM1 input gates (x-part + biases)
__device__ float g_h1out[BB * HH];       // LSTM1 final hidden
__device__ float g_xpre2[BB * G4];       // LSTM2 input gates

// HW tanh (sm_75+): 1 MUFU op; sigmoid via tanh identity
__device__ __forceinline__ float ftanh(float x) {
    float r; asm("tanh.approx.f32 %0, %1;" : "=f"(r) : "f"(x)); return r;
}
__device__ __forceinline__ float fsig(float x) {
    return fmaf(ftanh(0.5f * x), 0.5f, 0.5f);
}

// ---------------- zero scratch ----------------
__global__ void k_zero() {
    int i = blockIdx.x * 256 + threadIdx.x;
    if (i < NN) { g_deg[i] = 0.f; g_flag[i] = 0; }
    if (i < MAXSLOTS * HH) g_xagg[i] = 0.f;
    if (i < 8 * HH) g_hagg[i] = 0.f;
    if (i < 4) g_cnt[i] = 0;
}

// ---------------- edge pass 1: degree histogram + edges into targets ----------------
__global__ void k_scan1(const int* __restrict__ ei) {
    int e = blockIdx.x * 256 + threadIdx.x;
    if (e >= EE) return;
    int d = ei[EE + e];
    atomicAdd(&g_deg[d], 1.0f);
    if (d <= 7000 && (d % 1000) == 0) {   // TARGET = {0,1000,...,7000}
        int ti = d / 1000;
        int p = atomicAdd(&g_cnt[1], 1);
        if (p < MAXT) { g_tgt_src[p] = ei[e]; g_tgt_t[p] = ti; }
    }
}

// ---------------- dedupe target-edge sources into slots; slots 0..7 = targets ----------------
__global__ void k_dedupe() {
    __shared__ int s_src[MAXT];
    __shared__ int s_first[MAXT];
    __shared__ int s_slot[MAXT];
    int i = threadIdx.x;
    int nT = g_cnt[1]; if (nT > MAXT) nT = MAXT;
    if (i < 8) { g_flag[i * 1000] = i + 1; g_nodeOfSlot[i] = i * 1000; }
    int s = (i < nT) ? g_tgt_src[i] : -1;
    s_src[i] = s;
    __syncthreads();
    int slot = -1, first = 0;
    if (i < nT) {
        #pragma unroll
        for (int k = 0; k < 8; k++) if (s == k * 1000) slot = k;
        if (slot < 0) {
            first = 1;
            for (int j = 0; j < i; j++) if (s_src[j] == s) { first = 0; break; }
        }
    }
    s_first[i] = (i < nT && slot < 0) ? first : 0;
    s_slot[i] = slot;
    __syncthreads();
    if (i < nT && slot < 0) {
        if (first) {
            int rank = 0;
            for (int j = 0; j < i; j++) rank += s_first[j];
            s_slot[i] = 8 + rank;
        } else {
            int j = 0; while (s_src[j] != s) j++;
            int rj = 0;
            for (int q = 0; q < j; q++) rj += s_first[q];
            s_slot[i] = 8 + rj;
        }
    }
    __syncthreads();
    if (i < nT) {
        g_tgt_slot[i] = s_slot[i];
        if (s_first[i]) { g_nodeOfSlot[s_slot[i]] = s_src[i]; g_flag[s_src[i]] = s_slot[i] + 1; }
    }
    if (i == 0) {
        int tot = 0;
        for (int j = 0; j < nT; j++) tot += s_first[j];
        g_cnt[0] = 8 + tot;
    }
}

// ---------------- edge pass 2: edges whose dst is in the 1-hop set ----------------
__global__ void k_scan2(const int* __restrict__ ei) {
    int e = blockIdx.x * 256 + threadIdx.x;
    if (e >= EE) return;
    int d = ei[EE + e];
    int f = g_flag[d];
    if (f > 0) {
        int p = atomicAdd(&g_cnt[2], 1);
        if (p < MAXL1) { g_l1_src[p] = ei[e]; g_l1_slot[p] = f - 1; }
    }
}

// ---------------- GCN layer 1: aggregate RAW features per slot (linearity fold) ----------------
__global__ void k_l1agg(const float* __restrict__ x) {
    int cnt = g_cnt[2]; if (cnt > MAXL1) cnt = MAXL1;
    for (int idx = blockIdx.x; idx < cnt; idx += gridDim.x) {
        int src = g_l1_src[idx], slot = g_l1_slot[idx];
        int dn = g_nodeOfSlot[slot];
        float norm = rsqrtf(g_deg[src] + 1.f) * rsqrtf(g_deg[dn] + 1.f);
        atomicAdd(&g_xagg[slot * HH + threadIdx.x], x[src * HH + threadIdx.x] * norm);
    }
}

// ---------------- GCN layer 1: (agg + self) @ W1 + b1, relu -> g_h1 ----------------
__global__ void k_l1mat(const float* __restrict__ x, const float* __restrict__ W1,
                        const float* __restrict__ b1) {
    __shared__ float xs[HH];
    int nslots = g_cnt[0];
    for (int slot = blockIdx.x; slot < nslots; slot += gridDim.x) {
        int node = g_nodeOfSlot[slot];
        float rs = rsqrtf(g_deg[node] + 1.f);
        float di2 = rs * rs;
        __syncthreads();
        xs[threadIdx.x] = g_xagg[slot * HH + threadIdx.x] + x[node * HH + threadIdx.x] * di2;
        __syncthreads();
        float acc = 0.f;
        #pragma unroll 8
        for (int k = 0; k < HH; k++) acc += xs[k] * W1[k * HH + threadIdx.x];
        g_h1[slot * HH + threadIdx.x] = fmaxf(acc + b1[threadIdx.x], 0.f);
    }
}

// ---------------- GCN layer 2: aggregate h1 at the 8 targets (linearity fold) ----------------
__global__ void k_l2agg() {
    int cnt = g_cnt[1]; if (cnt > MAXT) cnt = MAXT;
    for (int i = blockIdx.x; i < cnt; i += gridDim.x) {
        int t = g_tgt_t[i], s = g_tgt_src[i], slot = g_tgt_slot[i];
        int tn = t * 1000;
        float norm = rsqrtf(g_deg[s] + 1.f) * rsqrtf(g_deg[tn] + 1.f);
        atomicAdd(&g_hagg[t * HH + threadIdx.x], g_h1[slot * HH + threadIdx.x] * norm);
    }
}

// ---------------- GCN layer 2: (agg + self) @ W2 + b2, relu -> g_dvec[0:1024] ----------------
__global__ void k_l2mat(const float* __restrict__ W2, const float* __restrict__ b2) {
    __shared__ float hs[HH];
    int t = blockIdx.x, o = threadIdx.x;
    int tn = t * 1000;
    float rs = rsqrtf(g_deg[tn] + 1.f);
    float di2 = rs * rs;
    hs[o] = g_hagg[t * HH + o] + g_h1[t * HH + o] * di2;   // slot t == target t
    __syncthreads();
    float acc = 0.f;
    #pragma unroll 8
    for (int k = 0; k < HH; k++) acc += hs[k] * W2[k * HH + o];
    g_dvec[t * HH + o] = fmaxf(acc + b2[o], 0.f);
}

// ---------------- LSTM1 input GEMM: xpre[t*32+b, n] = data0[b,t,:] @ Wih1[n,:] + bih1+bhh1 ----------------
__global__ __launch_bounds__(256) void k_xpre(const float* __restrict__ data0,
                                              const float* __restrict__ Wih1,
                                              const float* __restrict__ bih1,
                                              const float* __restrict__ bhh1) {
    __shared__ float xs[64][65];
    __shared__ float ws[64][65];   // ws[k][j]
    int rowbase = blockIdx.x * 64;
    int colbase = blockIdx.y * 64;
    int tid = threadIdx.x;
    for (int idx = tid; idx < 64 * 64; idx += 256) {
        int i = idx >> 6, k = idx & 63;
        int r = rowbase + i, b = r & 31, t = r >> 5;
        xs[i][k] = data0[(b * TT + t) * INQ + k];
    }
    for (int idx = tid; idx < 64 * 64; idx += 256) {
        int j = idx >> 6, k = idx & 63;
        ws[k][j] = Wih1[(colbase + j) * INQ + k];
    }
    __syncthreads();
    int tx = tid & 15, ty = tid >> 4;
    float acc[4][4] = {};
    #pragma unroll 8
    for (int k = 0; k < 64; k++) {
        float a[4], bb[4];
        #pragma unroll
        for (int u = 0; u < 4; u++) a[u] = xs[ty * 4 + u][k];
        #pragma unroll
        for (int v = 0; v < 4; v++) bb[v] = ws[k][tx * 4 + v];
        #pragma unroll
        for (int u = 0; u < 4; u++)
            #pragma unroll
            for (int v = 0; v < 4; v++) acc[u][v] = fmaf(a[u], bb[v], acc[u][v]);
    }
    #pragma unroll
    for (int u = 0; u < 4; u++) {
        int r = rowbase + ty * 4 + u;
        #pragma unroll
        for (int v = 0; v < 4; v++) {
            int n = colbase + tx * 4 + v;
            g_xpre[r * G4 + n] = acc[u][v] + bih1[n] + bhh1[n];
        }
    }
}

// ---------------- LSTM recurrence: 2-CTA cluster; quad-lane gate layout ----------------
// Thread tid: gate gt = tid&3 (i,f,g,o), h-offset m = tid>>2; hidx = rank*64+m.
// 4 gate values for one h-index sit in adjacent lanes -> shfl gather, no smem gate xchg.
// Only the 64-float h-chunk crosses CTAs per step (st.shared::cluster + mbarrier).
#define MBAR_WAIT_CL(addr, parity) do {                                            \
    asm volatile("{\n\t.reg .pred P;\n\t"                                          \
        "WL_%=:\n\t"                                                               \
        "mbarrier.try_wait.parity.acquire.cluster.shared::cta.b64 P, [%0], %1;\n\t"\
        "@P bra.uni WD_%=;\n\t"                                                    \
        "bra.uni WL_%=;\n\t"                                                       \
        "WD_%=:\n\t}"                                                              \
        :: "r"(addr), "r"(parity) : "memory");                                     \
} while (0)

__global__ __launch_bounds__(256, 1) __cluster_dims__(2, 1, 1)
void k_lstm_cl(const float* __restrict__ Whh, int steps, int which) {
    __shared__ __align__(16) float sh_h[2][HH];
    __shared__ __align__(8) unsigned long long smb[2];
    int tid = threadIdx.x;
    int rank = (int)(blockIdx.x & 1);
    int b = (int)(blockIdx.x >> 1);
    int gt = tid & 3;             // gate type 0..3 (i,f,g,o)
    int m  = tid >> 2;            // h-offset within my chunk (0..63)
    int hidx = (rank << 6) + m;   // global h index
    int row  = gt * HH + hidx;    // gate row this thread computes

    // one-time: weight row packed into 64 b64 registers
    unsigned long long wq[64];
    {
        const float4* w4 = (const float4*)(Whh + row * HH);
        #pragma unroll
        for (int q = 0; q < 32; q++) {
            float4 w = __ldg(&w4[q]);
            asm("mov.b64 %0, {%1,%2};" : "=l"(wq[2 * q])     : "f"(w.x), "f"(w.y));
            asm("mov.b64 %0, {%1,%2};" : "=l"(wq[2 * q + 1]) : "f"(w.z), "f"(w.w));
        }
    }

    if (tid < HH) sh_h[0][tid] = 0.f;
    if (tid == 0) {
        uint32_t b0 = (uint32_t)__cvta_generic_to_shared(&smb[0]);
        uint32_t b1 = (uint32_t)__cvta_generic_to_shared(&smb[1]);
        asm volatile("mbarrier.init.shared.b64 [%0], %1;" :: "r"(b0), "r"(64u));
        asm volatile("mbarrier.init.shared.b64 [%0], %1;" :: "r"(b1), "r"(64u));
    }

    uint32_t sh_base = (uint32_t)__cvta_generic_to_shared(&sh_h[0][0]);
    uint32_t lb0 = (uint32_t)__cvta_generic_to_shared(&smb[0]);
    uint32_t lb1 = (uint32_t)__cvta_generic_to_shared(&smb[1]);
    uint32_t lh0 = (uint32_t)__cvta_generic_to_shared(&sh_h[0][hidx]);
    uint32_t lh1 = (uint32_t)__cvta_generic_to_shared(&sh_h[1][hidx]);
    uint32_t peer = 1u ^ (uint32_t)rank;
    uint32_t rh0, rh1, rb0, rb1;
    asm("mapa.shared::cluster.u32 %0, %1, %2;" : "=r"(rh0) : "r"(lh0), "r"(peer));
    asm("mapa.shared::cluster.u32 %0, %1, %2;" : "=r"(rh1) : "r"(lh1), "r"(peer));
    asm("mapa.shared::cluster.u32 %0, %1, %2;" : "=r"(rb0) : "r"(lb0), "r"(peer));
    asm("mapa.shared::cluster.u32 %0, %1, %2;" : "=r"(rb1) : "r"(lb1), "r"(peer));
    __syncthreads();
    asm volatile("barrier.cluster.arrive.aligned;" ::: "memory");
    asm volatile("barrier.cluster.wait.aligned;" ::: "memory");

    int ph0 = 0, ph1 = 0;
    float c = 0.f;
    int qbase = (tid & 31) & ~3;   // quad base lane within warp
    float accn = (which == 1) ? g_xpre[b * G4 + row] : g_xpre2[row];
    for (int s = 0; s < steps; s++) {
        int buf = s & 1;
        if (s > 0) {
            if (buf) { MBAR_WAIT_CL(lb1, ph1); ph1 ^= 1; }
            else     { MBAR_WAIT_CL(lb0, ph0); ph0 ^= 1; }
        }
        float acc = accn;
        if (s + 1 < steps)
            accn = (which == 1) ? g_xpre[((s + 1) * BB + b) * G4 + row]
                                : g_xpre2[(s + 1) * G4 + row];

        // matvec over sh_h[buf] with packed f32x2 FMAs (broadcast LDS)
        unsigned long long a0 = 0ull, a1 = 0ull, a2 = 0ull, a3 = 0ull;
        uint32_t hb = sh_base + ((uint32_t)buf << 9);
        #pragma unroll
        for (int q = 0; q < 32; q++) {
            unsigned long long h01, h23;
            asm volatile("ld.shared.v2.u64 {%0,%1}, [%2];"
                         : "=l"(h01), "=l"(h23) : "r"(hb + q * 16));
            if (q & 1) {
                asm("fma.rn.f32x2 %0, %1, %2, %0;" : "+l"(a2) : "l"(wq[2 * q]),     "l"(h01));
                asm("fma.rn.f32x2 %0, %1, %2, %0;" : "+l"(a3) : "l"(wq[2 * q + 1]), "l"(h23));
            } else {
                asm("fma.rn.f32x2 %0, %1, %2, %0;" : "+l"(a0) : "l"(wq[2 * q]),     "l"(h01));
                asm("fma.rn.f32x2 %0, %1, %2, %0;" : "+l"(a1) : "l"(wq[2 * q + 1]), "l"(h23));
            }
        }
        asm("add.rn.f32x2 %0, %0, %1;" : "+l"(a0) : "l"(a2));
        asm("add.rn.f32x2 %0, %0, %1;" : "+l"(a1) : "l"(a3));
        float x0, y0, x1, y1;
        asm("mov.b64 {%0,%1}, %2;" : "=f"(x0), "=f"(y0) : "l"(a0));
        asm("mov.b64 {%0,%1}, %2;" : "=f"(x1), "=f"(y1) : "l"(a1));
        float v = acc + ((x0 + y0) + (x1 + y1));

        // quad gather: all 4 gate values for my m (adjacent lanes)
        float gi = __shfl_sync(0xffffffffu, v, qbase + 0);
        float gf = __shfl_sync(0xffffffffu, v, qbase + 1);
        float gg = __shfl_sync(0xffffffffu, v, qbase + 2);
        float go = __shfl_sync(0xffffffffu, v, qbase + 3);

        // redundant (consistent) c/h update in every lane of the quad
        c = fsig(gf) * c + fsig(gi) * ftanh(gg);
        float h = fsig(go) * ftanh(c);

        if (gt == 0) {
            if (s + 1 < steps) {
                int bn = (s + 1) & 1;
                sh_h[bn][hidx] = h;
                uint32_t rg = bn ? rh1 : rh0;
                uint32_t rb = bn ? rb1 : rb0;
                asm volatile("st.shared::cluster.f32 [%0], %1;" :: "r"(rg), "f"(h) : "memory");
                asm volatile("mbarrier.arrive.release.cluster.shared::cluster.b64 _, [%0];"
                             :: "r"(rb) : "memory");
            } else {
                if (which == 1) g_h1out[b * HH + hidx] = h;
                else            g_dvec[8 * HH + hidx] = h;
            }
        }
        __syncthreads();
    }
}

// ---------------- LSTM2 input GEMM: xpre2[s, n] = h1out[s,:] @ Wih2[n,:] + biases ----------------
__global__ __launch_bounds__(128) void k_xpre2(const float* __restrict__ Wih2,
                                               const float* __restrict__ bih2,
                                               const float* __restrict__ bhh2) {
    __shared__ float hh[BB * HH];
    int tid = threadIdx.x;
    for (int idx = tid; idx < BB * HH; idx += 128) hh[idx] = g_h1out[idx];
    __syncthreads();
    int n = blockIdx.x * 128 + tid;
    float4 wreg[32];
    const float4* w4 = (const float4*)(Wih2 + n * HH);
    #pragma unroll
    for (int kk = 0; kk < 32; kk++) wreg[kk] = __ldg(&w4[kk]);
    float bias = bih2[n] + bhh2[n];
    for (int s = 0; s < BB; s++) {
        const float4* h4 = (const float4*)(hh + s * HH);
        float a0 = 0.f, a1 = 0.f, a2 = 0.f, a3 = 0.f;
        #pragma unroll
        for (int kk = 0; kk < 32; kk++) {
            float4 h = h4[kk];
            a0 = fmaf(wreg[kk].x, h.x, a0); a1 = fmaf(wreg[kk].y, h.y, a1);
            a2 = fmaf(wreg[kk].z, h.z, a2); a3 = fmaf(wreg[kk].w, h.w, a3);
        }
        g_xpre2[s * G4 + n] = bias + ((a0 + a1) + (a2 + a3));
    }
}

// ---------------- MLP head: fuse m1_w @ m2_w (no nonlinearity in head) ----------------
__global__ void k_fw(const float* __restrict__ m1w, const float* __restrict__ m2w) {
    int i = blockIdx.x;
    float s = 0.f;
    for (int j = threadIdx.x; j < 576; j += 64) s += m1w[i * 576 + j] * m2w[j];
    #pragma unroll
    for (int off = 16; off > 0; off >>= 1) s += __shfl_down_sync(0xffffffffu, s, off);
    __shared__ float sm[2];
    if ((threadIdx.x & 31) == 0) sm[threadIdx.x >> 5] = s;
    __syncthreads();
    if (threadIdx.x == 0) g_fw[i] = sm[0] + sm[1];
}

__global__ void k_final(const float* __restrict__ m1b, const float* __restrict__ m2w,
                        const float* __restrict__ m2b, float* __restrict__ out) {
    __shared__ float red[512];
    float s = 0.f;
    for (int i = threadIdx.x; i < 9 * HH; i += 512) s += g_dvec[i] * g_fw[i];
    for (int j = threadIdx.x; j < 576; j += 512) s += m1b[j] * m2w[j];
    red[threadIdx.x] = s;
    __syncthreads();
    for (int st = 256; st > 0; st >>= 1) {
        if (threadIdx.x < st) red[threadIdx.x] += red[threadIdx.x + st];
        __syncthreads();
    }
    if (threadIdx.x == 0) out[0] = red[0] + m2b[0];
}

// ---------------- launch ----------------
extern "C" void kernel_launch(void* const* d_in, const int* in_sizes, int n_in,
                              void* d_out, int out_size) {
    const float* data0 = (const float*)d_in[0];
    const float* data1 = (const float*)d_in[1];
    const int*   ei    = (const int*)d_in[2];
    const float* W1   = (const float*)d_in[3];
    const float* b1   = (const float*)d_in[4];
    const float* W2   = (const float*)d_in[5];
    const float* b2   = (const float*)d_in[6];
    const float* Wih1 = (const float*)d_in[7];
    const float* Whh1 = (const float*)d_in[8];
    const float* bih1 = (const float*)d_in[9];
    const float* bhh1 = (const float*)d_in[10];
    const float* Wih2 = (const float*)d_in[11];
    const float* Whh2 = (const float*)d_in[12];
    const float* bih2 = (const float*)d_in[13];
    const float* bhh2 = (const float*)d_in[14];
    const float* m1w  = (const float*)d_in[15];
    const float* m1b  = (const float*)d_in[16];
    const float* m2w  = (const float*)d_in[17];
    const float* m2b  = (const float*)d_in[18];
    float* out = (float*)d_out;

    static cudaStream_t s2 = nullptr;
    static cudaEvent_t evA = nullptr, evB = nullptr;
    if (!s2) {
        cudaStreamCreateWithFlags(&s2, cudaStreamNonBlocking);
        cudaEventCreateWithFlags(&evA, cudaEventDisableTiming);
        cudaEventCreateWithFlags(&evB, cudaEventDisableTiming);
    }

    // fork: GCN chain + head-weight fold run on s2, LSTM chain on default stream.
    // Host launch order puts k_lstm_cl 4th so ncu's fixed capture slot profiles it.
    cudaEventRecord(evA, 0);
    cudaStreamWaitEvent(s2, evA, 0);

    k_xpre<<<dim3(100, 8), 256>>>(data0, Wih1, bih1, bhh1);          // launch 1 (default)
    k_zero<<<(MAXSLOTS * HH + 255) / 256, 256, 0, s2>>>();           // launch 2 (s2)
    k_scan1<<<(EE + 255) / 256, 256, 0, s2>>>(ei);                   // launch 3 (s2)
    k_lstm_cl<<<2 * BB, 256>>>(Whh1, TT, 1);                         // launch 4 (default) <- ncu slot
    k_dedupe<<<1, MAXT, 0, s2>>>();                                  // launch 5 (s2)
    k_scan2<<<(EE + 255) / 256, 256, 0, s2>>>(ei);                   // launch 6 (s2)
    k_l1agg<<<256, HH, 0, s2>>>(data1);
    k_l1mat<<<128, HH, 0, s2>>>(data1, W1, b1);
    k_l2agg<<<64, HH, 0, s2>>>();
    k_l2mat<<<8, HH, 0, s2>>>(W2, b2);
    k_fw<<<1152, 64, 0, s2>>>(m1w, m2w);

    k_xpre2<<<4, 128>>>(Wih2, bih2, bhh2);
    k_lstm_cl<<<2, 256>>>(Whh2, BB, 2);

    // join
    cudaEventRecord(evB, s2);
    cudaStreamWaitEvent(0, evB, 0);
    k_final<<<1, 512>>>(m1b, m2w, m2b, out);
}